// round 1
// baseline (speedup 1.0000x reference)
#include <cuda_runtime.h>
#include <cstdint>

#define NB 32
#define S  512
#define D  512

// Scratch (device globals: allocation-free per harness rules)
__device__ float g_E [ (size_t)NB * S * S ];   // 32 MB scores
__device__ float g_PA[ (size_t)NB * S * S ];   // 32 MB attn_a
__device__ float g_cmax[ NB * S ];
__device__ float g_cinv[ NB * S ];

// ---------------------------------------------------------------------------
// Shared-mem tile loaders. Tiles are 16(K) x 128 stored K-outer: sm[k][mn].
// ---------------------------------------------------------------------------

// Source row-major [rows x ld], tile = 128 rows x 16 cols, store transposed.
__device__ __forceinline__ void load_tile_T(const float* __restrict__ src, int ld,
                                            float sm[16][128], int t) {
#pragma unroll
    for (int p = 0; p < 2; ++p) {
        int fl  = t + p * 256;      // 0..511
        int row = fl >> 2;          // 0..127
        int kq  = (fl & 3) << 2;    // 0,4,8,12
        float4 v = *(const float4*)(src + (size_t)row * ld + kq);
        sm[kq + 0][row] = v.x;
        sm[kq + 1][row] = v.y;
        sm[kq + 2][row] = v.z;
        sm[kq + 3][row] = v.w;
    }
}

// Source row-major [rows x ld], tile = 16 rows x 128 cols, store direct.
__device__ __forceinline__ void load_tile_N(const float* __restrict__ src, int ld,
                                            float sm[16][128], int t) {
#pragma unroll
    for (int p = 0; p < 2; ++p) {
        int fl  = t + p * 256;
        int row = fl >> 5;          // 0..15
        int cq  = (fl & 31) << 2;   // 0..124
        float4 v = *(const float4*)(src + (size_t)row * ld + cq);
        *(float4*)&sm[row][cq] = v;
    }
}

__device__ __forceinline__ void mma_tile(const float (*As)[128], const float (*Bs)[128],
                                         float acc[8][8], int r0, int c0) {
#pragma unroll
    for (int kk = 0; kk < 16; ++kk) {
        float ar[8], br[8];
#pragma unroll
        for (int m = 0; m < 8; ++m) ar[m] = As[kk][r0 + m];
#pragma unroll
        for (int n = 0; n < 8; ++n) br[n] = Bs[kk][c0 + n];
#pragma unroll
        for (int m = 0; m < 8; ++m)
#pragma unroll
            for (int n = 0; n < 8; ++n)
                acc[m][n] = fmaf(ar[m], br[n], acc[m][n]);
    }
}

// ---------------------------------------------------------------------------
// K1: E[b,i,j] = sum_d a[b,i,d] * bm[b,j,d]
// grid (S/128 j-tiles, S/128 i-tiles, NB), 256 threads
// ---------------------------------------------------------------------------
__global__ __launch_bounds__(256)
void gemm_e_kernel(const float* __restrict__ a, const float* __restrict__ bm) {
    int b  = blockIdx.z;
    int i0 = blockIdx.y * 128;
    int j0 = blockIdx.x * 128;
    __shared__ float As[16][128];   // [k][i]
    __shared__ float Bs[16][128];   // [k][j]
    const float* ab = a  + (size_t)b * S * D;
    const float* bb = bm + (size_t)b * S * D;
    float acc[8][8] = {};
    int t  = threadIdx.x;
    int r0 = (t >> 4) << 3;
    int c0 = (t & 15) << 3;
    for (int k0 = 0; k0 < D; k0 += 16) {
        load_tile_T(ab + (size_t)i0 * D + k0, D, As, t);
        load_tile_T(bb + (size_t)j0 * D + k0, D, Bs, t);
        __syncthreads();
        mma_tile(As, Bs, acc, r0, c0);
        __syncthreads();
    }
    float* Eb = g_E + (size_t)b * S * S;
#pragma unroll
    for (int m = 0; m < 8; ++m) {
        int i = i0 + r0 + m;
#pragma unroll
        for (int n = 0; n < 8; n += 4) {
            float4 v = make_float4(acc[m][n], acc[m][n+1], acc[m][n+2], acc[m][n+3]);
            *(float4*)(Eb + (size_t)i * S + j0 + c0 + n) = v;
        }
    }
}

// ---------------------------------------------------------------------------
// K2a: row softmax over j -> g_PA. One block per (b,i) row. 256 threads.
// ---------------------------------------------------------------------------
__global__ __launch_bounds__(256)
void row_softmax_kernel() {
    size_t row = blockIdx.x;
    const float* e  = g_E  + row * S;
    float*       pa = g_PA + row * S;
    int t = threadIdx.x;
    float v0 = e[t], v1 = e[t + 256];
    float m = fmaxf(v0, v1);
    __shared__ float red[8];
#pragma unroll
    for (int o = 16; o; o >>= 1) m = fmaxf(m, __shfl_xor_sync(0xffffffffu, m, o));
    if ((t & 31) == 0) red[t >> 5] = m;
    __syncthreads();
    m = fmaxf(fmaxf(fmaxf(red[0], red[1]), fmaxf(red[2], red[3])),
              fmaxf(fmaxf(red[4], red[5]), fmaxf(red[6], red[7])));
    float e0 = __expf(v0 - m), e1 = __expf(v1 - m);
    float s = e0 + e1;
#pragma unroll
    for (int o = 16; o; o >>= 1) s += __shfl_xor_sync(0xffffffffu, s, o);
    __syncthreads();
    if ((t & 31) == 0) red[t >> 5] = s;
    __syncthreads();
    s = (red[0] + red[1]) + (red[2] + red[3]) + (red[4] + red[5]) + (red[6] + red[7]);
    float inv = 1.0f / s;
    pa[t]       = e0 * inv;
    pa[t + 256] = e1 * inv;
}

// ---------------------------------------------------------------------------
// K2b: column stats (softmax over i): online max/sum per column j.
// grid (S/64, NB), 256 threads = 64 cols x 4 row-slices.
// ---------------------------------------------------------------------------
__global__ __launch_bounds__(256)
void col_stats_kernel() {
    int b  = blockIdx.y;
    int j0 = blockIdx.x * 64;
    int c  = threadIdx.x & 63;
    int r  = threadIdx.x >> 6;     // 0..3
    int j  = j0 + c;
    const float* e = g_E + (size_t)b * S * S + j;
    float m = -3.402823466e38f, s = 0.0f;
    for (int i = r * 128; i < (r + 1) * 128; ++i) {
        float v  = e[(size_t)i * S];
        float nm = fmaxf(m, v);
        s = s * __expf(m - nm) + __expf(v - nm);
        m = nm;
    }
    __shared__ float sm[4][64], ss[4][64];
    sm[r][c] = m; ss[r][c] = s;
    __syncthreads();
    if (r == 0) {
        float M = m, Sv = s;
#pragma unroll
        for (int q = 1; q < 4; ++q) {
            float m2 = sm[q][c], s2 = ss[q][c];
            float nm = fmaxf(M, m2);
            Sv = Sv * __expf(M - nm) + s2 * __expf(m2 - nm);
            M = nm;
        }
        g_cmax[b * S + j] = M;
        g_cinv[b * S + j] = 1.0f / Sv;
    }
}

// ---------------------------------------------------------------------------
// K3: a_tilde = attn_a @ bm, fused m_a epilogue.
// grid (D/128 d-tiles, S/128 i-tiles, NB)
// ---------------------------------------------------------------------------
__global__ __launch_bounds__(256)
void gemm_a_kernel(const float* __restrict__ a, const float* __restrict__ bm,
                   float* __restrict__ out) {
    int b  = blockIdx.z;
    int i0 = blockIdx.y * 128;
    int d0 = blockIdx.x * 128;
    __shared__ float Ps[16][128];   // [j][i]
    __shared__ float Bs[16][128];   // [j][d]
    const float* PA = g_PA + (size_t)b * S * S;
    const float* bb = bm   + (size_t)b * S * D;
    float acc[8][8] = {};
    int t  = threadIdx.x;
    int r0 = (t >> 4) << 3;
    int c0 = (t & 15) << 3;
    for (int k0 = 0; k0 < S; k0 += 16) {
        load_tile_T(PA + (size_t)i0 * S + k0, S, Ps, t);
        load_tile_N(bb + (size_t)k0 * D + d0, D, Bs, t);
        __syncthreads();
        mma_tile(Ps, Bs, acc, r0, c0);
        __syncthreads();
    }
    const float* ab = a + (size_t)b * S * D;
#pragma unroll
    for (int m = 0; m < 8; ++m) {
        int i = i0 + r0 + m;
#pragma unroll
        for (int n = 0; n < 8; n += 4) {
            int d = d0 + c0 + n;
            float4 av = *(const float4*)(ab + (size_t)i * D + d);
            float4 tv = make_float4(acc[m][n], acc[m][n+1], acc[m][n+2], acc[m][n+3]);
            size_t ob = ((size_t)b * S + i) * 2048 + d;
            *(float4*)(out + ob)        = av;
            *(float4*)(out + ob + 512)  = tv;
            *(float4*)(out + ob + 1024) = make_float4(av.x - tv.x, av.y - tv.y,
                                                      av.z - tv.z, av.w - tv.w);
            *(float4*)(out + ob + 1536) = make_float4(av.x * tv.x, av.y * tv.y,
                                                      av.z * tv.z, av.w * tv.w);
        }
    }
}

// ---------------------------------------------------------------------------
// K4: b_tilde[j,d] = sum_i softmax_col(E)[i,j] * a[i,d], attn built on the fly.
// grid (D/128 d-tiles, S/128 j-tiles, NB). Fused m_b epilogue.
// ---------------------------------------------------------------------------
__global__ __launch_bounds__(256)
void gemm_b_kernel(const float* __restrict__ a, const float* __restrict__ bm,
                   float* __restrict__ out) {
    int b  = blockIdx.z;
    int j0 = blockIdx.y * 128;
    int d0 = blockIdx.x * 128;
    __shared__ float Ps[16][128];   // [i][j] = attn_b^T tile
    __shared__ float As[16][128];   // [i][d]
    __shared__ float cm_s[128], ci_s[128];
    const float* Eb = g_E + (size_t)b * S * S;
    const float* ab = a   + (size_t)b * S * D;
    int t = threadIdx.x;
    if (t < 128) {
        cm_s[t] = g_cmax[b * S + j0 + t];
        ci_s[t] = g_cinv[b * S + j0 + t];
    }
    __syncthreads();
    float acc[8][8] = {};
    int r0 = (t >> 4) << 3;   // j
    int c0 = (t & 15) << 3;   // d
    for (int k0 = 0; k0 < S; k0 += 16) {   // k = i
        // P tile: exp(E[i, j] - cmax[j]) * cinv[j], already [i][j] layout
#pragma unroll
        for (int p = 0; p < 2; ++p) {
            int fl = t + p * 256;
            int ii = fl >> 5;
            int jq = (fl & 31) << 2;
            float4 v = *(const float4*)(Eb + (size_t)(k0 + ii) * S + j0 + jq);
            Ps[ii][jq + 0] = __expf(v.x - cm_s[jq + 0]) * ci_s[jq + 0];
            Ps[ii][jq + 1] = __expf(v.y - cm_s[jq + 1]) * ci_s[jq + 1];
            Ps[ii][jq + 2] = __expf(v.z - cm_s[jq + 2]) * ci_s[jq + 2];
            Ps[ii][jq + 3] = __expf(v.w - cm_s[jq + 3]) * ci_s[jq + 3];
        }
        load_tile_N(ab + (size_t)k0 * D + d0, D, As, t);
        __syncthreads();
        mma_tile(Ps, As, acc, r0, c0);
        __syncthreads();
    }
    const float* bb = bm + (size_t)b * S * D;
    const size_t MB_BASE = (size_t)NB * S * 2048;
#pragma unroll
    for (int m = 0; m < 8; ++m) {
        int j = j0 + r0 + m;
#pragma unroll
        for (int n = 0; n < 8; n += 4) {
            int d = d0 + c0 + n;
            float4 bv = *(const float4*)(bb + (size_t)j * D + d);
            float4 tv = make_float4(acc[m][n], acc[m][n+1], acc[m][n+2], acc[m][n+3]);
            size_t ob = MB_BASE + ((size_t)b * S + j) * 2048 + d;
            *(float4*)(out + ob)        = bv;
            *(float4*)(out + ob + 512)  = tv;
            *(float4*)(out + ob + 1024) = make_float4(bv.x - tv.x, bv.y - tv.y,
                                                      bv.z - tv.z, bv.w - tv.w);
            *(float4*)(out + ob + 1536) = make_float4(bv.x * tv.x, bv.y * tv.y,
                                                      bv.z * tv.z, bv.w * tv.w);
        }
    }
}

// ---------------------------------------------------------------------------

extern "C" void kernel_launch(void* const* d_in, const int* in_sizes, int n_in,
                              void* d_out, int out_size) {
    const float* a  = (const float*)d_in[0];
    const float* bm = (const float*)d_in[1];
    float* out = (float*)d_out;
    (void)in_sizes; (void)n_in; (void)out_size;

    dim3 gtile(S / 128, S / 128, NB);          // (4,4,32)
    gemm_e_kernel<<<gtile, 256>>>(a, bm);
    row_softmax_kernel<<<NB * S, 256>>>();
    col_stats_kernel<<<dim3(S / 64, NB), 256>>>();
    gemm_a_kernel<<<gtile, 256>>>(a, bm, out);
    gemm_b_kernel<<<gtile, 256>>>(a, bm, out);
}

// round 4
// speedup vs baseline: 1.6932x; 1.6932x over previous
#include <cuda_runtime.h>
#include <cuda_bf16.h>
#include <mma.h>
#include <cstdint>

using namespace nvcuda;

#define NB 32
#define S  512
#define NC 16            // K chunks of 32 (K=512)

// ---------------------------------------------------------------------------
// Device-global scratch (allocation-free per harness rules)
// ---------------------------------------------------------------------------
__device__ __align__(16) float g_E[(size_t)NB * S * S];   // 32 MB scores
__device__ float g_rmax[NB * S], g_rinv[NB * S];          // row softmax stats
__device__ float g_cmax[NB * S], g_cinv[NB * S];          // col softmax stats

// smem pitches (elements)
#define PMK 40     // [128 rows][k-chunk 32] bf16 tile, padded (80 B/row)
#define PKN 136    // [k 32][n 128] bf16 tile, padded (272 B/row)
#define PFS 136    // [128][128] f32 epilogue staging, padded (544 B/row)

__device__ __forceinline__ void split2(float x, __nv_bfloat16& h, __nv_bfloat16& l) {
    h = __float2bfloat16(x);
    l = __float2bfloat16(x - __bfloat162float(h));
}

// ---------------------------------------------------------------------------
// Tile staging: gmem fp32 -> regs -> (split bf16) -> smem
// ---------------------------------------------------------------------------
// [m=128][k=32] tile; src pre-offset to (row0, k0); 256 threads x 4 float4
__device__ __forceinline__ void ld_mk(const float* __restrict__ src, float4 r[4], int t) {
#pragma unroll
    for (int p = 0; p < 4; ++p) {
        int idx = t + p * 256, row = idx >> 3, c = idx & 7;
        r[p] = *(const float4*)(src + (size_t)row * S + c * 4);
    }
}
// [k=32][n=128] tile; src pre-offset to (k0, n0)
__device__ __forceinline__ void ld_kn(const float* __restrict__ src, float4 r[4], int t) {
#pragma unroll
    for (int p = 0; p < 4; ++p) {
        int idx = t + p * 256, row = idx >> 5, c = idx & 31;
        r[p] = *(const float4*)(src + (size_t)row * S + c * 4);
    }
}

__device__ __forceinline__ void pack_store(char* hi, char* lo, int byteoff,
                                           float x0, float x1, float x2, float x3) {
    __nv_bfloat16 h, l;
    unsigned short hh[4], ll[4];
    split2(x0, h, l); hh[0] = __bfloat16_as_ushort(h); ll[0] = __bfloat16_as_ushort(l);
    split2(x1, h, l); hh[1] = __bfloat16_as_ushort(h); ll[1] = __bfloat16_as_ushort(l);
    split2(x2, h, l); hh[2] = __bfloat16_as_ushort(h); ll[2] = __bfloat16_as_ushort(l);
    split2(x3, h, l); hh[3] = __bfloat16_as_ushort(h); ll[3] = __bfloat16_as_ushort(l);
    *(ushort4*)(hi + byteoff) = make_ushort4(hh[0], hh[1], hh[2], hh[3]);
    *(ushort4*)(lo + byteoff) = make_ushort4(ll[0], ll[1], ll[2], ll[3]);
}

__device__ __forceinline__ void st_mk(char* hi, char* lo, const float4 r[4], int t) {
#pragma unroll
    for (int p = 0; p < 4; ++p) {
        int idx = t + p * 256, row = idx >> 3, c = idx & 7;
        pack_store(hi, lo, row * 80 + c * 8, r[p].x, r[p].y, r[p].z, r[p].w);
    }
}
// row-softmax applied per m-row (stats indexed by local row)
__device__ __forceinline__ void st_mk_soft(char* hi, char* lo, const float4 r[4], int t,
                                           const float* rs, const float* ri) {
#pragma unroll
    for (int p = 0; p < 4; ++p) {
        int idx = t + p * 256, row = idx >> 3, c = idx & 7;
        float m = rs[row], iv = ri[row];
        pack_store(hi, lo, row * 80 + c * 8,
                   __expf(r[p].x - m) * iv, __expf(r[p].y - m) * iv,
                   __expf(r[p].z - m) * iv, __expf(r[p].w - m) * iv);
    }
}
__device__ __forceinline__ void st_kn(char* hi, char* lo, const float4 r[4], int t) {
#pragma unroll
    for (int p = 0; p < 4; ++p) {
        int idx = t + p * 256, row = idx >> 5, c = idx & 31;
        pack_store(hi, lo, row * 272 + c * 8, r[p].x, r[p].y, r[p].z, r[p].w);
    }
}
// col-softmax applied per n-slot (stats indexed by local fast axis)
__device__ __forceinline__ void st_kn_soft(char* hi, char* lo, const float4 r[4], int t,
                                           const float* cs, const float* ci) {
#pragma unroll
    for (int p = 0; p < 4; ++p) {
        int idx = t + p * 256, row = idx >> 5, c = idx & 31;
        int n = c * 4;
        pack_store(hi, lo, row * 272 + c * 8,
                   __expf(r[p].x - cs[n + 0]) * ci[n + 0],
                   __expf(r[p].y - cs[n + 1]) * ci[n + 1],
                   __expf(r[p].z - cs[n + 2]) * ci[n + 2],
                   __expf(r[p].w - cs[n + 3]) * ci[n + 3]);
    }
}

// ---------------------------------------------------------------------------
// wmma compute cores (warp tile 64m x 32n; acc[4][2])
// ---------------------------------------------------------------------------
typedef wmma::fragment<wmma::accumulator, 16, 16, 16, float> FragC;

#define MMA3(acc, ah, al, bh, bl) do {            \
    wmma::mma_sync(acc, ah, bh, acc);             \
    wmma::mma_sync(acc, ah, bl, acc);             \
    wmma::mma_sync(acc, al, bh, acc); } while (0)

// MODE 0 (E = a.b^T): A row-major [m][k], B col-major (tile stored [n][k])
__device__ __forceinline__ void compute_E(const char* st, FragC acc[4][2], int wm, int wn) {
    const __nv_bfloat16* Ah = (const __nv_bfloat16*)(st);
    const __nv_bfloat16* Al = (const __nv_bfloat16*)(st + 10240);
    const __nv_bfloat16* Bh = (const __nv_bfloat16*)(st + 20480);
    const __nv_bfloat16* Bl = (const __nv_bfloat16*)(st + 30720);
#pragma unroll
    for (int ks = 0; ks < 2; ++ks) {
        wmma::fragment<wmma::matrix_a, 16, 16, 16, __nv_bfloat16, wmma::row_major> fah[4], fal[4];
        wmma::fragment<wmma::matrix_b, 16, 16, 16, __nv_bfloat16, wmma::col_major> fbh[2], fbl[2];
#pragma unroll
        for (int mi = 0; mi < 4; ++mi) {
            int r = (wm * 64 + mi * 16) * PMK + ks * 16;
            wmma::load_matrix_sync(fah[mi], Ah + r, PMK);
            wmma::load_matrix_sync(fal[mi], Al + r, PMK);
        }
#pragma unroll
        for (int ni = 0; ni < 2; ++ni) {
            int r = (wn * 32 + ni * 16) * PMK + ks * 16;
            wmma::load_matrix_sync(fbh[ni], Bh + r, PMK);
            wmma::load_matrix_sync(fbl[ni], Bl + r, PMK);
        }
#pragma unroll
        for (int mi = 0; mi < 4; ++mi)
#pragma unroll
            for (int ni = 0; ni < 2; ++ni)
                MMA3(acc[mi][ni], fah[mi], fal[mi], fbh[ni], fbl[ni]);
    }
}

// MODE 1 (a_tilde = P.b): A row-major [m][k], B row-major (tile [k][n])
__device__ __forceinline__ void compute_A(const char* st, FragC acc[4][2], int wm, int wn) {
    const __nv_bfloat16* Ah = (const __nv_bfloat16*)(st);
    const __nv_bfloat16* Al = (const __nv_bfloat16*)(st + 10240);
    const __nv_bfloat16* Bh = (const __nv_bfloat16*)(st + 20480);
    const __nv_bfloat16* Bl = (const __nv_bfloat16*)(st + 29184);
#pragma unroll
    for (int ks = 0; ks < 2; ++ks) {
        wmma::fragment<wmma::matrix_a, 16, 16, 16, __nv_bfloat16, wmma::row_major> fah[4], fal[4];
        wmma::fragment<wmma::matrix_b, 16, 16, 16, __nv_bfloat16, wmma::row_major> fbh[2], fbl[2];
#pragma unroll
        for (int mi = 0; mi < 4; ++mi) {
            int r = (wm * 64 + mi * 16) * PMK + ks * 16;
            wmma::load_matrix_sync(fah[mi], Ah + r, PMK);
            wmma::load_matrix_sync(fal[mi], Al + r, PMK);
        }
#pragma unroll
        for (int ni = 0; ni < 2; ++ni) {
            int r = ks * 16 * PKN + wn * 32 + ni * 16;
            wmma::load_matrix_sync(fbh[ni], Bh + r, PKN);
            wmma::load_matrix_sync(fbl[ni], Bl + r, PKN);
        }
#pragma unroll
        for (int mi = 0; mi < 4; ++mi)
#pragma unroll
            for (int ni = 0; ni < 2; ++ni)
                MMA3(acc[mi][ni], fah[mi], fal[mi], fbh[ni], fbl[ni]);
    }
}

// MODE 2 (b_tilde = P^T.a): A col-major (tile [k][m]), B row-major (tile [k][n])
__device__ __forceinline__ void compute_B(const char* st, FragC acc[4][2], int wm, int wn) {
    const __nv_bfloat16* Ah = (const __nv_bfloat16*)(st);
    const __nv_bfloat16* Al = (const __nv_bfloat16*)(st + 8704);
    const __nv_bfloat16* Bh = (const __nv_bfloat16*)(st + 17408);
    const __nv_bfloat16* Bl = (const __nv_bfloat16*)(st + 26112);
#pragma unroll
    for (int ks = 0; ks < 2; ++ks) {
        wmma::fragment<wmma::matrix_a, 16, 16, 16, __nv_bfloat16, wmma::col_major> fah[4], fal[4];
        wmma::fragment<wmma::matrix_b, 16, 16, 16, __nv_bfloat16, wmma::row_major> fbh[2], fbl[2];
#pragma unroll
        for (int mi = 0; mi < 4; ++mi) {
            int r = ks * 16 * PKN + wm * 64 + mi * 16;
            wmma::load_matrix_sync(fah[mi], Ah + r, PKN);
            wmma::load_matrix_sync(fal[mi], Al + r, PKN);
        }
#pragma unroll
        for (int ni = 0; ni < 2; ++ni) {
            int r = ks * 16 * PKN + wn * 32 + ni * 16;
            wmma::load_matrix_sync(fbh[ni], Bh + r, PKN);
            wmma::load_matrix_sync(fbl[ni], Bl + r, PKN);
        }
#pragma unroll
        for (int mi = 0; mi < 4; ++mi)
#pragma unroll
            for (int ni = 0; ni < 2; ++ni)
                MMA3(acc[mi][ni], fah[mi], fal[mi], fbh[ni], fbl[ni]);
    }
}

// ---------------------------------------------------------------------------
// Generic GEMM kernel. MODE: 0=E, 1=a_tilde+m_a, 2=b_tilde+m_b
// Block 128x128, 256 threads, double-buffered k-chunks of 32.
// ---------------------------------------------------------------------------
template <int MODE>
__global__ __launch_bounds__(256)
void k_gemm(const float* __restrict__ a, const float* __restrict__ bm,
            float* __restrict__ out) {
    constexpr int STAGE = (MODE == 0) ? 40960 : (MODE == 1) ? 37888 : 34816;
    extern __shared__ char sm[];
    int t = threadIdx.x, wid = t >> 5;
    int wm = wid & 1, wn = wid >> 1;
    int bb = blockIdx.z, m0 = blockIdx.y * 128, n0 = blockIdx.x * 128;
    const size_t SS = (size_t)S * S;

    // stats preload (modes 1/2)
    float* rs = (float*)(sm + 2 * STAGE);
    float* ri = rs + 128;
    if (MODE == 1) {
        if (t < 128) { rs[t] = g_rmax[bb * S + m0 + t]; ri[t] = g_rinv[bb * S + m0 + t]; }
    } else if (MODE == 2) {
        if (t < 128) { rs[t] = g_cmax[bb * S + m0 + t]; ri[t] = g_cinv[bb * S + m0 + t]; }
    }
    if (MODE != 0) __syncthreads();

    // source pointers
    const float* srcA;
    const float* srcB;
    if (MODE == 0) { srcA = a + bb * SS + (size_t)m0 * S;   srcB = bm + bb * SS + (size_t)n0 * S; }
    if (MODE == 1) { srcA = g_E + bb * SS + (size_t)m0 * S; srcB = bm + bb * SS + n0; }
    if (MODE == 2) { srcA = g_E + bb * SS + m0;             srcB = a + bb * SS + n0; }

    FragC acc[4][2];
#pragma unroll
    for (int mi = 0; mi < 4; ++mi)
#pragma unroll
        for (int ni = 0; ni < 2; ++ni) wmma::fill_fragment(acc[mi][ni], 0.0f);

    float4 rA[4], rB[4];

#define LOAD_REGS(c) do {                                                       \
        if (MODE == 2) ld_kn(srcA + (size_t)(c) * 32 * S, rA, t);               \
        else           ld_mk(srcA + (c) * 32, rA, t);                           \
        if (MODE == 0) ld_mk(srcB + (c) * 32, rB, t);                           \
        else           ld_kn(srcB + (size_t)(c) * 32 * S, rB, t); } while (0)

#define STORE_REGS(s) do { char* st_ = sm + (s) * STAGE;                        \
        if (MODE == 0)      st_mk(st_, st_ + 10240, rA, t);                     \
        else if (MODE == 1) st_mk_soft(st_, st_ + 10240, rA, t, rs, ri);        \
        else                st_kn_soft(st_, st_ + 8704, rA, t, rs, ri);         \
        if (MODE == 0)      st_mk(st_ + 20480, st_ + 30720, rB, t);             \
        else if (MODE == 1) st_kn(st_ + 20480, st_ + 29184, rB, t);             \
        else                st_kn(st_ + 17408, st_ + 26112, rB, t); } while (0)

    LOAD_REGS(0);
    STORE_REGS(0);

#pragma unroll 1
    for (int c = 0; c < NC; ++c) {
        __syncthreads();
        if (c + 1 < NC) LOAD_REGS(c + 1);
        const char* stage = sm + (c & 1) * STAGE;
        if (MODE == 0)      compute_E(stage, acc, wm, wn);
        else if (MODE == 1) compute_A(stage, acc, wm, wn);
        else                compute_B(stage, acc, wm, wn);
        if (c + 1 < NC) STORE_REGS((c + 1) & 1);
    }
    __syncthreads();

    if (MODE == 0) {
        // direct store of E tile to gmem
        float* Eb = g_E + bb * SS + (size_t)m0 * S + n0;
#pragma unroll
        for (int mi = 0; mi < 4; ++mi)
#pragma unroll
            for (int ni = 0; ni < 2; ++ni)
                wmma::store_matrix_sync(Eb + (size_t)(wm * 64 + mi * 16) * S + wn * 32 + ni * 16,
                                        acc[mi][ni], S, wmma::mem_row_major);
        return;
    }

    // modes 1/2: stage result through smem, fused 4-way concat epilogue
    float* fs = (float*)sm;   // [128][PFS]
#pragma unroll
    for (int mi = 0; mi < 4; ++mi)
#pragma unroll
        for (int ni = 0; ni < 2; ++ni)
            wmma::store_matrix_sync(fs + (size_t)(wm * 64 + mi * 16) * PFS + wn * 32 + ni * 16,
                                    acc[mi][ni], PFS, wmma::mem_row_major);
    __syncthreads();

    const float* base = (MODE == 1) ? (a + ((size_t)bb * S + m0) * S + n0)
                                    : (bm + ((size_t)bb * S + m0) * S + n0);
    size_t obase = ((size_t)bb * S + m0) * 2048 + n0;
    if (MODE == 2) obase += (size_t)NB * S * 2048;
    float* ob = out + obase;
#pragma unroll
    for (int p = 0; p < 16; ++p) {
        int idx = t + p * 256;
        int r = idx >> 5, d4 = idx & 31;
        float4 xv = *(const float4*)(base + (size_t)r * S + 4 * d4);
        float4 tv = *(const float4*)(fs + (size_t)r * PFS + 4 * d4);
        float* o = ob + (size_t)r * 2048 + 4 * d4;
        *(float4*)(o)        = xv;
        *(float4*)(o + 512)  = tv;
        *(float4*)(o + 1024) = make_float4(xv.x - tv.x, xv.y - tv.y, xv.z - tv.z, xv.w - tv.w);
        *(float4*)(o + 1536) = make_float4(xv.x * tv.x, xv.y * tv.y, xv.z * tv.z, xv.w * tv.w);
    }
#undef LOAD_REGS
#undef STORE_REGS
}

// ---------------------------------------------------------------------------
// Row softmax stats: one warp per row
// ---------------------------------------------------------------------------
__global__ __launch_bounds__(256)
void k_row_stats() {
    int wid = threadIdx.x >> 5, lane = threadIdx.x & 31;
    size_t row = (size_t)blockIdx.x * 8 + wid;
    const float* e = g_E + row * S;
    float4 v[4];
#pragma unroll
    for (int p = 0; p < 4; ++p) v[p] = *(const float4*)(e + lane * 4 + p * 128);
    float m = -3.402823466e38f;
#pragma unroll
    for (int p = 0; p < 4; ++p)
        m = fmaxf(m, fmaxf(fmaxf(v[p].x, v[p].y), fmaxf(v[p].z, v[p].w)));
#pragma unroll
    for (int o = 16; o; o >>= 1) m = fmaxf(m, __shfl_xor_sync(0xffffffffu, m, o));
    float s = 0.0f;
#pragma unroll
    for (int p = 0; p < 4; ++p)
        s += __expf(v[p].x - m) + __expf(v[p].y - m) + __expf(v[p].z - m) + __expf(v[p].w - m);
#pragma unroll
    for (int o = 16; o; o >>= 1) s += __shfl_xor_sync(0xffffffffu, s, o);
    if (lane == 0) { g_rmax[row] = m; g_rinv[row] = 1.0f / s; }
}

// ---------------------------------------------------------------------------
// Column softmax stats (over i), online. 64 cols x 4 row-slices per block.
// ---------------------------------------------------------------------------
__global__ __launch_bounds__(256)
void k_col_stats() {
    int b  = blockIdx.y;
    int j0 = blockIdx.x * 64;
    int c  = threadIdx.x & 63;
    int r  = threadIdx.x >> 6;
    int j  = j0 + c;
    const float* e = g_E + (size_t)b * S * S + j;
    float m = -3.402823466e38f, s = 0.0f;
    for (int i = r * 128; i < (r + 1) * 128; ++i) {
        float v  = e[(size_t)i * S];
        float nm = fmaxf(m, v);
        s = s * __expf(m - nm) + __expf(v - nm);
        m = nm;
    }
    __shared__ float sm2[4][64], ss2[4][64];
    sm2[r][c] = m; ss2[r][c] = s;
    __syncthreads();
    if (r == 0) {
        float M = m, Sv = s;
#pragma unroll
        for (int q = 1; q < 4; ++q) {
            float m2 = sm2[q][c], s2 = ss2[q][c];
            float nm = fmaxf(M, m2);
            Sv = Sv * __expf(M - nm) + s2 * __expf(m2 - nm);
            M = nm;
        }
        g_cmax[b * S + j] = M;
        g_cinv[b * S + j] = 1.0f / Sv;
    }
}

// ---------------------------------------------------------------------------

extern "C" void kernel_launch(void* const* d_in, const int* in_sizes, int n_in,
                              void* d_out, int out_size) {
    const float* a  = (const float*)d_in[0];
    const float* bm = (const float*)d_in[1];
    float* out = (float*)d_out;
    (void)in_sizes; (void)n_in; (void)out_size;

    static int configured = 0;
    if (!configured) {
        cudaFuncSetAttribute(k_gemm<0>, cudaFuncAttributeMaxDynamicSharedMemorySize, 2 * 40960);
        cudaFuncSetAttribute(k_gemm<1>, cudaFuncAttributeMaxDynamicSharedMemorySize, 2 * 37888 + 1024);
        cudaFuncSetAttribute(k_gemm<2>, cudaFuncAttributeMaxDynamicSharedMemorySize, 2 * 34816 + 1024);
        configured = 1;
    }

    dim3 gg(4, 4, NB);   // (n-tiles, m-tiles, batch)
    k_gemm<0><<<gg, 256, 2 * 40960>>>(a, bm, out);
    k_row_stats<<<NB * S / 8, 256>>>();
    k_col_stats<<<dim3(S / 64, NB), 256>>>();
    k_gemm<1><<<gg, 256, 2 * 37888 + 1024>>>(a, bm, out);
    k_gemm<2><<<gg, 256, 2 * 34816 + 1024>>>(a, bm, out);
}

// round 5
// speedup vs baseline: 1.7572x; 1.0378x over previous
#include <cuda_runtime.h>
#include <cuda_bf16.h>
#include <mma.h>
#include <cstdint>

using namespace nvcuda;

#define NB 32
#define S  512
#define NC 16            // K chunks of 32 (K=512)
#define NT 512           // threads per GEMM block

// ---------------------------------------------------------------------------
// Device-global scratch (allocation-free per harness rules)
// ---------------------------------------------------------------------------
__device__ __align__(16) float g_E[(size_t)NB * S * S];   // 32 MB scores
__device__ float g_rmax[NB * S], g_rinv[NB * S];          // row softmax stats
__device__ float g_cmax[NB * S], g_cinv[NB * S];          // col softmax stats

// smem pitches (elements)
#define PMK 40     // [128 rows][k-chunk 32] bf16 tile, padded (80 B/row)
#define PKN 136    // [k 32][n 128] bf16 tile, padded (272 B/row)
#define PFS 136    // [128][128] f32 epilogue staging, padded (544 B/row)

__device__ __forceinline__ void split2(float x, __nv_bfloat16& h, __nv_bfloat16& l) {
    h = __float2bfloat16(x);
    l = __float2bfloat16(x - __bfloat162float(h));
}

// ---------------------------------------------------------------------------
// Tile staging: gmem fp32 -> regs -> (split bf16) -> smem.  512 threads.
// ---------------------------------------------------------------------------
// [m=128][k=32] tile; src pre-offset to (row0, k0); 512 threads x 2 float4
__device__ __forceinline__ void ld_mk(const float* __restrict__ src, float4 r[2], int t) {
#pragma unroll
    for (int p = 0; p < 2; ++p) {
        int idx = t + p * NT, row = idx >> 3, c = idx & 7;
        r[p] = *(const float4*)(src + (size_t)row * S + c * 4);
    }
}
// [k=32][n=128] tile; src pre-offset to (k0, n0)
__device__ __forceinline__ void ld_kn(const float* __restrict__ src, float4 r[2], int t) {
#pragma unroll
    for (int p = 0; p < 2; ++p) {
        int idx = t + p * NT, row = idx >> 5, c = idx & 31;
        r[p] = *(const float4*)(src + (size_t)row * S + c * 4);
    }
}

__device__ __forceinline__ void pack_store(char* hi, char* lo, int byteoff,
                                           float x0, float x1, float x2, float x3) {
    __nv_bfloat16 h, l;
    unsigned short hh[4], ll[4];
    split2(x0, h, l); hh[0] = __bfloat16_as_ushort(h); ll[0] = __bfloat16_as_ushort(l);
    split2(x1, h, l); hh[1] = __bfloat16_as_ushort(h); ll[1] = __bfloat16_as_ushort(l);
    split2(x2, h, l); hh[2] = __bfloat16_as_ushort(h); ll[2] = __bfloat16_as_ushort(l);
    split2(x3, h, l); hh[3] = __bfloat16_as_ushort(h); ll[3] = __bfloat16_as_ushort(l);
    *(ushort4*)(hi + byteoff) = make_ushort4(hh[0], hh[1], hh[2], hh[3]);
    *(ushort4*)(lo + byteoff) = make_ushort4(ll[0], ll[1], ll[2], ll[3]);
}

__device__ __forceinline__ void st_mk(char* hi, char* lo, const float4 r[2], int t) {
#pragma unroll
    for (int p = 0; p < 2; ++p) {
        int idx = t + p * NT, row = idx >> 3, c = idx & 7;
        pack_store(hi, lo, row * 80 + c * 8, r[p].x, r[p].y, r[p].z, r[p].w);
    }
}
// row-softmax applied per m-row (stats indexed by local row)
__device__ __forceinline__ void st_mk_soft(char* hi, char* lo, const float4 r[2], int t,
                                           const float* rs, const float* ri) {
#pragma unroll
    for (int p = 0; p < 2; ++p) {
        int idx = t + p * NT, row = idx >> 3, c = idx & 7;
        float m = rs[row], iv = ri[row];
        pack_store(hi, lo, row * 80 + c * 8,
                   __expf(r[p].x - m) * iv, __expf(r[p].y - m) * iv,
                   __expf(r[p].z - m) * iv, __expf(r[p].w - m) * iv);
    }
}
__device__ __forceinline__ void st_kn(char* hi, char* lo, const float4 r[2], int t) {
#pragma unroll
    for (int p = 0; p < 2; ++p) {
        int idx = t + p * NT, row = idx >> 5, c = idx & 31;
        pack_store(hi, lo, row * 272 + c * 8, r[p].x, r[p].y, r[p].z, r[p].w);
    }
}
// col-softmax applied per n-slot (stats indexed by local fast axis)
__device__ __forceinline__ void st_kn_soft(char* hi, char* lo, const float4 r[2], int t,
                                           const float* cs, const float* ci) {
#pragma unroll
    for (int p = 0; p < 2; ++p) {
        int idx = t + p * NT, row = idx >> 5, c = idx & 31;
        int n = c * 4;
        pack_store(hi, lo, row * 272 + c * 8,
                   __expf(r[p].x - cs[n + 0]) * ci[n + 0],
                   __expf(r[p].y - cs[n + 1]) * ci[n + 1],
                   __expf(r[p].z - cs[n + 2]) * ci[n + 2],
                   __expf(r[p].w - cs[n + 3]) * ci[n + 3]);
    }
}

// ---------------------------------------------------------------------------
// wmma compute cores (16 warps, warp tile 32m x 32n; acc[2][2])
// ---------------------------------------------------------------------------
typedef wmma::fragment<wmma::accumulator, 16, 16, 16, float> FragC;

#define MMA3(acc, ah, al, bh, bl) do {            \
    wmma::mma_sync(acc, ah, bh, acc);             \
    wmma::mma_sync(acc, ah, bl, acc);             \
    wmma::mma_sync(acc, al, bh, acc); } while (0)

// MODE 0 (E = a.b^T): A row-major [m][k], B col-major (tile stored [n][k])
__device__ __forceinline__ void compute_E(const char* st, FragC acc[2][2], int wm, int wn) {
    const __nv_bfloat16* Ah = (const __nv_bfloat16*)(st);
    const __nv_bfloat16* Al = (const __nv_bfloat16*)(st + 10240);
    const __nv_bfloat16* Bh = (const __nv_bfloat16*)(st + 20480);
    const __nv_bfloat16* Bl = (const __nv_bfloat16*)(st + 30720);
#pragma unroll
    for (int ks = 0; ks < 2; ++ks) {
        wmma::fragment<wmma::matrix_a, 16, 16, 16, __nv_bfloat16, wmma::row_major> fah[2], fal[2];
        wmma::fragment<wmma::matrix_b, 16, 16, 16, __nv_bfloat16, wmma::col_major> fbh[2], fbl[2];
#pragma unroll
        for (int mi = 0; mi < 2; ++mi) {
            int r = (wm * 32 + mi * 16) * PMK + ks * 16;
            wmma::load_matrix_sync(fah[mi], Ah + r, PMK);
            wmma::load_matrix_sync(fal[mi], Al + r, PMK);
        }
#pragma unroll
        for (int ni = 0; ni < 2; ++ni) {
            int r = (wn * 32 + ni * 16) * PMK + ks * 16;
            wmma::load_matrix_sync(fbh[ni], Bh + r, PMK);
            wmma::load_matrix_sync(fbl[ni], Bl + r, PMK);
        }
#pragma unroll
        for (int mi = 0; mi < 2; ++mi)
#pragma unroll
            for (int ni = 0; ni < 2; ++ni)
                MMA3(acc[mi][ni], fah[mi], fal[mi], fbh[ni], fbl[ni]);
    }
}

// MODE 1 (a_tilde = P.b): A row-major [m][k], B row-major (tile [k][n])
__device__ __forceinline__ void compute_A(const char* st, FragC acc[2][2], int wm, int wn) {
    const __nv_bfloat16* Ah = (const __nv_bfloat16*)(st);
    const __nv_bfloat16* Al = (const __nv_bfloat16*)(st + 10240);
    const __nv_bfloat16* Bh = (const __nv_bfloat16*)(st + 20480);
    const __nv_bfloat16* Bl = (const __nv_bfloat16*)(st + 29184);
#pragma unroll
    for (int ks = 0; ks < 2; ++ks) {
        wmma::fragment<wmma::matrix_a, 16, 16, 16, __nv_bfloat16, wmma::row_major> fah[2], fal[2];
        wmma::fragment<wmma::matrix_b, 16, 16, 16, __nv_bfloat16, wmma::row_major> fbh[2], fbl[2];
#pragma unroll
        for (int mi = 0; mi < 2; ++mi) {
            int r = (wm * 32 + mi * 16) * PMK + ks * 16;
            wmma::load_matrix_sync(fah[mi], Ah + r, PMK);
            wmma::load_matrix_sync(fal[mi], Al + r, PMK);
        }
#pragma unroll
        for (int ni = 0; ni < 2; ++ni) {
            int r = ks * 16 * PKN + wn * 32 + ni * 16;
            wmma::load_matrix_sync(fbh[ni], Bh + r, PKN);
            wmma::load_matrix_sync(fbl[ni], Bl + r, PKN);
        }
#pragma unroll
        for (int mi = 0; mi < 2; ++mi)
#pragma unroll
            for (int ni = 0; ni < 2; ++ni)
                MMA3(acc[mi][ni], fah[mi], fal[mi], fbh[ni], fbl[ni]);
    }
}

// MODE 2 (b_tilde = P^T.a): A col-major (tile [k][m]), B row-major (tile [k][n])
__device__ __forceinline__ void compute_B(const char* st, FragC acc[2][2], int wm, int wn) {
    const __nv_bfloat16* Ah = (const __nv_bfloat16*)(st);
    const __nv_bfloat16* Al = (const __nv_bfloat16*)(st + 8704);
    const __nv_bfloat16* Bh = (const __nv_bfloat16*)(st + 17408);
    const __nv_bfloat16* Bl = (const __nv_bfloat16*)(st + 26112);
#pragma unroll
    for (int ks = 0; ks < 2; ++ks) {
        wmma::fragment<wmma::matrix_a, 16, 16, 16, __nv_bfloat16, wmma::col_major> fah[2], fal[2];
        wmma::fragment<wmma::matrix_b, 16, 16, 16, __nv_bfloat16, wmma::row_major> fbh[2], fbl[2];
#pragma unroll
        for (int mi = 0; mi < 2; ++mi) {
            int r = ks * 16 * PKN + wm * 32 + mi * 16;
            wmma::load_matrix_sync(fah[mi], Ah + r, PKN);
            wmma::load_matrix_sync(fal[mi], Al + r, PKN);
        }
#pragma unroll
        for (int ni = 0; ni < 2; ++ni) {
            int r = ks * 16 * PKN + wn * 32 + ni * 16;
            wmma::load_matrix_sync(fbh[ni], Bh + r, PKN);
            wmma::load_matrix_sync(fbl[ni], Bl + r, PKN);
        }
#pragma unroll
        for (int mi = 0; mi < 2; ++mi)
#pragma unroll
            for (int ni = 0; ni < 2; ++ni)
                MMA3(acc[mi][ni], fah[mi], fal[mi], fbh[ni], fbl[ni]);
    }
}

// ---------------------------------------------------------------------------
// Generic GEMM kernel. MODE: 0=E, 1=a_tilde+m_a, 2=b_tilde+m_b
// Block tile 128x128, 512 threads (16 warps, warp tile 32x32),
// double-buffered k-chunks of 32.
// ---------------------------------------------------------------------------
template <int MODE>
__global__ __launch_bounds__(NT)
void k_gemm(const float* __restrict__ a, const float* __restrict__ bm,
            float* __restrict__ out) {
    constexpr int STAGE = (MODE == 0) ? 40960 : (MODE == 1) ? 37888 : 34816;
    extern __shared__ char sm[];
    int t = threadIdx.x, wid = t >> 5;
    int wm = wid & 3, wn = wid >> 2;
    int bb = blockIdx.z, m0 = blockIdx.y * 128, n0 = blockIdx.x * 128;
    const size_t SS = (size_t)S * S;

    // stats preload (modes 1/2)
    float* rs = (float*)(sm + 2 * STAGE);
    float* ri = rs + 128;
    if (MODE == 1) {
        if (t < 128) { rs[t] = g_rmax[bb * S + m0 + t]; ri[t] = g_rinv[bb * S + m0 + t]; }
    } else if (MODE == 2) {
        if (t < 128) { rs[t] = g_cmax[bb * S + m0 + t]; ri[t] = g_cinv[bb * S + m0 + t]; }
    }
    if (MODE != 0) __syncthreads();

    // source pointers
    const float* srcA;
    const float* srcB;
    if (MODE == 0) { srcA = a + bb * SS + (size_t)m0 * S;   srcB = bm + bb * SS + (size_t)n0 * S; }
    if (MODE == 1) { srcA = g_E + bb * SS + (size_t)m0 * S; srcB = bm + bb * SS + n0; }
    if (MODE == 2) { srcA = g_E + bb * SS + m0;             srcB = a + bb * SS + n0; }

    FragC acc[2][2];
#pragma unroll
    for (int mi = 0; mi < 2; ++mi)
#pragma unroll
        for (int ni = 0; ni < 2; ++ni) wmma::fill_fragment(acc[mi][ni], 0.0f);

    float4 rA[2], rB[2];

#define LOAD_REGS(c) do {                                                       \
        if (MODE == 2) ld_kn(srcA + (size_t)(c) * 32 * S, rA, t);               \
        else           ld_mk(srcA + (c) * 32, rA, t);                           \
        if (MODE == 0) ld_mk(srcB + (c) * 32, rB, t);                           \
        else           ld_kn(srcB + (size_t)(c) * 32 * S, rB, t); } while (0)

#define STORE_REGS(s) do { char* st_ = sm + (s) * STAGE;                        \
        if (MODE == 0)      st_mk(st_, st_ + 10240, rA, t);                     \
        else if (MODE == 1) st_mk_soft(st_, st_ + 10240, rA, t, rs, ri);        \
        else                st_kn_soft(st_, st_ + 8704, rA, t, rs, ri);         \
        if (MODE == 0)      st_mk(st_ + 20480, st_ + 30720, rB, t);             \
        else if (MODE == 1) st_kn(st_ + 20480, st_ + 29184, rB, t);             \
        else                st_kn(st_ + 17408, st_ + 26112, rB, t); } while (0)

    LOAD_REGS(0);
    STORE_REGS(0);

#pragma unroll 1
    for (int c = 0; c < NC; ++c) {
        __syncthreads();
        if (c + 1 < NC) LOAD_REGS(c + 1);
        const char* stage = sm + (c & 1) * STAGE;
        if (MODE == 0)      compute_E(stage, acc, wm, wn);
        else if (MODE == 1) compute_A(stage, acc, wm, wn);
        else                compute_B(stage, acc, wm, wn);
        if (c + 1 < NC) STORE_REGS((c + 1) & 1);
    }
    __syncthreads();

    if (MODE == 0) {
        // direct store of E tile to gmem
        float* Eb = g_E + bb * SS + (size_t)m0 * S + n0;
#pragma unroll
        for (int mi = 0; mi < 2; ++mi)
#pragma unroll
            for (int ni = 0; ni < 2; ++ni)
                wmma::store_matrix_sync(Eb + (size_t)(wm * 32 + mi * 16) * S + wn * 32 + ni * 16,
                                        acc[mi][ni], S, wmma::mem_row_major);
        return;
    }

    // modes 1/2: stage result through smem, fused 4-way concat epilogue
    float* fs = (float*)sm;   // [128][PFS]
#pragma unroll
    for (int mi = 0; mi < 2; ++mi)
#pragma unroll
        for (int ni = 0; ni < 2; ++ni)
            wmma::store_matrix_sync(fs + (size_t)(wm * 32 + mi * 16) * PFS + wn * 32 + ni * 16,
                                    acc[mi][ni], PFS, wmma::mem_row_major);
    __syncthreads();

    const float* base = (MODE == 1) ? (a + ((size_t)bb * S + m0) * S + n0)
                                    : (bm + ((size_t)bb * S + m0) * S + n0);
    size_t obase = ((size_t)bb * S + m0) * 2048 + n0;
    if (MODE == 2) obase += (size_t)NB * S * 2048;
    float* ob = out + obase;
#pragma unroll
    for (int p = 0; p < 8; ++p) {
        int idx = t + p * NT;
        int r = idx >> 5, d4 = idx & 31;
        float4 xv = *(const float4*)(base + (size_t)r * S + 4 * d4);
        float4 tv = *(const float4*)(fs + (size_t)r * PFS + 4 * d4);
        float* o = ob + (size_t)r * 2048 + 4 * d4;
        *(float4*)(o)        = xv;
        *(float4*)(o + 512)  = tv;
        *(float4*)(o + 1024) = make_float4(xv.x - tv.x, xv.y - tv.y, xv.z - tv.z, xv.w - tv.w);
        *(float4*)(o + 1536) = make_float4(xv.x * tv.x, xv.y * tv.y, xv.z * tv.z, xv.w * tv.w);
    }
#undef LOAD_REGS
#undef STORE_REGS
}

// ---------------------------------------------------------------------------
// Row softmax stats: one warp per row
// ---------------------------------------------------------------------------
__global__ __launch_bounds__(256)
void k_row_stats() {
    int wid = threadIdx.x >> 5, lane = threadIdx.x & 31;
    size_t row = (size_t)blockIdx.x * 8 + wid;
    const float* e = g_E + row * S;
    float4 v[4];
#pragma unroll
    for (int p = 0; p < 4; ++p) v[p] = *(const float4*)(e + lane * 4 + p * 128);
    float m = -3.402823466e38f;
#pragma unroll
    for (int p = 0; p < 4; ++p)
        m = fmaxf(m, fmaxf(fmaxf(v[p].x, v[p].y), fmaxf(v[p].z, v[p].w)));
#pragma unroll
    for (int o = 16; o; o >>= 1) m = fmaxf(m, __shfl_xor_sync(0xffffffffu, m, o));
    float s = 0.0f;
#pragma unroll
    for (int p = 0; p < 4; ++p)
        s += __expf(v[p].x - m) + __expf(v[p].y - m) + __expf(v[p].z - m) + __expf(v[p].w - m);
#pragma unroll
    for (int o = 16; o; o >>= 1) s += __shfl_xor_sync(0xffffffffu, s, o);
    if (lane == 0) { g_rmax[row] = m; g_rinv[row] = 1.0f / s; }
}

// ---------------------------------------------------------------------------
// Column softmax stats (over i), online. 64 cols x 4 row-slices per block.
// ---------------------------------------------------------------------------
__global__ __launch_bounds__(256)
void k_col_stats() {
    int b  = blockIdx.y;
    int j0 = blockIdx.x * 64;
    int c  = threadIdx.x & 63;
    int r  = threadIdx.x >> 6;
    int j  = j0 + c;
    const float* e = g_E + (size_t)b * S * S + j;
    float m = -3.402823466e38f, s = 0.0f;
    for (int i = r * 128; i < (r + 1) * 128; ++i) {
        float v  = e[(size_t)i * S];
        float nm = fmaxf(m, v);
        s = s * __expf(m - nm) + __expf(v - nm);
        m = nm;
    }
    __shared__ float sm2[4][64], ss2[4][64];
    sm2[r][c] = m; ss2[r][c] = s;
    __syncthreads();
    if (r == 0) {
        float M = m, Sv = s;
#pragma unroll
        for (int q = 1; q < 4; ++q) {
            float m2 = sm2[q][c], s2 = ss2[q][c];
            float nm = fmaxf(M, m2);
            Sv = Sv * __expf(M - nm) + s2 * __expf(m2 - nm);
            M = nm;
        }
        g_cmax[b * S + j] = M;
        g_cinv[b * S + j] = 1.0f / Sv;
    }
}

// ---------------------------------------------------------------------------

extern "C" void kernel_launch(void* const* d_in, const int* in_sizes, int n_in,
                              void* d_out, int out_size) {
    const float* a  = (const float*)d_in[0];
    const float* bm = (const float*)d_in[1];
    float* out = (float*)d_out;
    (void)in_sizes; (void)n_in; (void)out_size;

    static int configured = 0;
    if (!configured) {
        cudaFuncSetAttribute(k_gemm<0>, cudaFuncAttributeMaxDynamicSharedMemorySize, 2 * 40960);
        cudaFuncSetAttribute(k_gemm<1>, cudaFuncAttributeMaxDynamicSharedMemorySize, 2 * 37888 + 1024);
        cudaFuncSetAttribute(k_gemm<2>, cudaFuncAttributeMaxDynamicSharedMemorySize, 2 * 34816 + 1024);
        configured = 1;
    }

    dim3 gg(4, 4, NB);   // (n-tiles, m-tiles, batch)
    k_gemm<0><<<gg, NT, 2 * 40960>>>(a, bm, out);
    k_row_stats<<<NB * S / 8, 256>>>();
    k_col_stats<<<dim3(S / 64, NB), 256>>>();
    k_gemm<1><<<gg, NT, 2 * 37888 + 1024>>>(a, bm, out);
    k_gemm<2><<<gg, NT, 2 * 34816 + 1024>>>(a, bm, out);
}

// round 6
// speedup vs baseline: 1.8192x; 1.0353x over previous
#include <cuda_runtime.h>
#include <cuda_bf16.h>
#include <mma.h>
#include <cstdint>

using namespace nvcuda;

#define NB 32
#define S  512
#define NC 16            // K chunks of 32 (K=512)
#define NT 512           // threads per GEMM block
#define RAWS 3           // raw fp32 cp.async stages

// ---------------------------------------------------------------------------
// Device-global scratch (allocation-free per harness rules)
// ---------------------------------------------------------------------------
__device__ __align__(16) float g_E[(size_t)NB * S * S];   // 32 MB scores
__device__ float g_rmax[NB * S], g_rinv[NB * S];          // row softmax stats
__device__ float g_cmax[NB * S], g_cinv[NB * S];          // col softmax stats

// smem pitches (elements)
#define PMK 40     // [128 rows][k 32] bf16 tile, padded (80 B/row)
#define PKN 136    // [k 32][n 128] bf16 tile, padded (272 B/row)
#define PFS 136    // [128][128] f32 epilogue staging

#define RAW_BYTES 32768            // one raw stage: A 16KB + B 16KB fp32
#define BST_OFF   (RAWS * RAW_BYTES)

// ---------------------------------------------------------------------------
// cp.async helpers (Ampere+ generic PTX; valid at compute_103)
// ---------------------------------------------------------------------------
__device__ __forceinline__ void cp16(uint32_t dst, const void* src) {
    asm volatile("cp.async.cg.shared.global [%0], [%1], 16;" :: "r"(dst), "l"(src));
}
#define CP_COMMIT() asm volatile("cp.async.commit_group;" ::: "memory")
#define CP_WAIT(n)  asm volatile("cp.async.wait_group %0;" :: "n"(n) : "memory")

__device__ __forceinline__ void split2(float x, __nv_bfloat16& h, __nv_bfloat16& l) {
    h = __float2bfloat16(x);
    l = __float2bfloat16(x - __bfloat162float(h));
}

__device__ __forceinline__ void pack_store(char* hi, char* lo, int byteoff,
                                           float x0, float x1, float x2, float x3) {
    __nv_bfloat16 h, l;
    unsigned short hh[4], ll[4];
    split2(x0, h, l); hh[0] = __bfloat16_as_ushort(h); ll[0] = __bfloat16_as_ushort(l);
    split2(x1, h, l); hh[1] = __bfloat16_as_ushort(h); ll[1] = __bfloat16_as_ushort(l);
    split2(x2, h, l); hh[2] = __bfloat16_as_ushort(h); ll[2] = __bfloat16_as_ushort(l);
    split2(x3, h, l); hh[3] = __bfloat16_as_ushort(h); ll[3] = __bfloat16_as_ushort(l);
    *(ushort4*)(hi + byteoff) = make_ushort4(hh[0], hh[1], hh[2], hh[3]);
    *(ushort4*)(lo + byteoff) = make_ushort4(ll[0], ll[1], ll[2], ll[3]);
}

// ---------------------------------------------------------------------------
// gmem -> raw smem (cp.async).  [m=128][k=32] fp32 pitch 128B; [k=32][n=128] pitch 512B.
// ---------------------------------------------------------------------------
__device__ __forceinline__ void cp_mk(const float* __restrict__ src, uint32_t rawu, int t) {
#pragma unroll
    for (int p = 0; p < 2; ++p) {
        int idx = t + p * NT, row = idx >> 3, c = idx & 7;
        cp16(rawu + row * 128 + c * 16, src + (size_t)row * S + c * 4);
    }
}
__device__ __forceinline__ void cp_kn(const float* __restrict__ src, uint32_t rawu, int t) {
#pragma unroll
    for (int p = 0; p < 2; ++p) {
        int idx = t + p * NT, row = idx >> 5, c = idx & 31;
        cp16(rawu + row * 512 + c * 16, src + (size_t)row * S + c * 4);
    }
}

// ---------------------------------------------------------------------------
// raw smem -> split bf16 smem (each thread converts the chunks it copied)
// ---------------------------------------------------------------------------
__device__ __forceinline__ void cv_mk(const char* raw, char* hi, char* lo, int t) {
#pragma unroll
    for (int p = 0; p < 2; ++p) {
        int idx = t + p * NT, row = idx >> 3, c = idx & 7;
        float4 v = *(const float4*)(raw + row * 128 + c * 16);
        pack_store(hi, lo, row * 80 + c * 8, v.x, v.y, v.z, v.w);
    }
}
__device__ __forceinline__ void cv_mk_soft(const char* raw, char* hi, char* lo, int t,
                                           const float* rs, const float* ri) {
#pragma unroll
    for (int p = 0; p < 2; ++p) {
        int idx = t + p * NT, row = idx >> 3, c = idx & 7;
        float4 v = *(const float4*)(raw + row * 128 + c * 16);
        float m = rs[row], iv = ri[row];
        pack_store(hi, lo, row * 80 + c * 8,
                   __expf(v.x - m) * iv, __expf(v.y - m) * iv,
                   __expf(v.z - m) * iv, __expf(v.w - m) * iv);
    }
}
__device__ __forceinline__ void cv_kn(const char* raw, char* hi, char* lo, int t) {
#pragma unroll
    for (int p = 0; p < 2; ++p) {
        int idx = t + p * NT, row = idx >> 5, c = idx & 31;
        float4 v = *(const float4*)(raw + row * 512 + c * 16);
        pack_store(hi, lo, row * 272 + c * 8, v.x, v.y, v.z, v.w);
    }
}
__device__ __forceinline__ void cv_kn_soft(const char* raw, char* hi, char* lo, int t,
                                           const float* cs, const float* ci) {
#pragma unroll
    for (int p = 0; p < 2; ++p) {
        int idx = t + p * NT, row = idx >> 5, c = idx & 31;
        float4 v = *(const float4*)(raw + row * 512 + c * 16);
        int n = c * 4;
        pack_store(hi, lo, row * 272 + c * 8,
                   __expf(v.x - cs[n + 0]) * ci[n + 0],
                   __expf(v.y - cs[n + 1]) * ci[n + 1],
                   __expf(v.z - cs[n + 2]) * ci[n + 2],
                   __expf(v.w - cs[n + 3]) * ci[n + 3]);
    }
}

// ---------------------------------------------------------------------------
// wmma compute cores (16 warps, warp tile 32m x 32n; acc[2][2])
// ---------------------------------------------------------------------------
typedef wmma::fragment<wmma::accumulator, 16, 16, 16, float> FragC;

#define MMA3(acc, ah, al, bh, bl) do {            \
    wmma::mma_sync(acc, ah, bh, acc);             \
    wmma::mma_sync(acc, ah, bl, acc);             \
    wmma::mma_sync(acc, al, bh, acc); } while (0)

// MODE 0 (E = a.b^T): A row-major [m][k], B col-major (tile stored [n][k])
__device__ __forceinline__ void compute_E(const char* st, FragC acc[2][2], int wm, int wn) {
    const __nv_bfloat16* Ah = (const __nv_bfloat16*)(st);
    const __nv_bfloat16* Al = (const __nv_bfloat16*)(st + 10240);
    const __nv_bfloat16* Bh = (const __nv_bfloat16*)(st + 20480);
    const __nv_bfloat16* Bl = (const __nv_bfloat16*)(st + 30720);
#pragma unroll
    for (int ks = 0; ks < 2; ++ks) {
        wmma::fragment<wmma::matrix_a, 16, 16, 16, __nv_bfloat16, wmma::row_major> fah[2], fal[2];
        wmma::fragment<wmma::matrix_b, 16, 16, 16, __nv_bfloat16, wmma::col_major> fbh[2], fbl[2];
#pragma unroll
        for (int mi = 0; mi < 2; ++mi) {
            int r = (wm * 32 + mi * 16) * PMK + ks * 16;
            wmma::load_matrix_sync(fah[mi], Ah + r, PMK);
            wmma::load_matrix_sync(fal[mi], Al + r, PMK);
        }
#pragma unroll
        for (int ni = 0; ni < 2; ++ni) {
            int r = (wn * 32 + ni * 16) * PMK + ks * 16;
            wmma::load_matrix_sync(fbh[ni], Bh + r, PMK);
            wmma::load_matrix_sync(fbl[ni], Bl + r, PMK);
        }
#pragma unroll
        for (int mi = 0; mi < 2; ++mi)
#pragma unroll
            for (int ni = 0; ni < 2; ++ni)
                MMA3(acc[mi][ni], fah[mi], fal[mi], fbh[ni], fbl[ni]);
    }
}

// MODE 1 (a_tilde = P.b): A row-major [m][k], B row-major (tile [k][n])
__device__ __forceinline__ void compute_A(const char* st, FragC acc[2][2], int wm, int wn) {
    const __nv_bfloat16* Ah = (const __nv_bfloat16*)(st);
    const __nv_bfloat16* Al = (const __nv_bfloat16*)(st + 10240);
    const __nv_bfloat16* Bh = (const __nv_bfloat16*)(st + 20480);
    const __nv_bfloat16* Bl = (const __nv_bfloat16*)(st + 29184);
#pragma unroll
    for (int ks = 0; ks < 2; ++ks) {
        wmma::fragment<wmma::matrix_a, 16, 16, 16, __nv_bfloat16, wmma::row_major> fah[2], fal[2];
        wmma::fragment<wmma::matrix_b, 16, 16, 16, __nv_bfloat16, wmma::row_major> fbh[2], fbl[2];
#pragma unroll
        for (int mi = 0; mi < 2; ++mi) {
            int r = (wm * 32 + mi * 16) * PMK + ks * 16;
            wmma::load_matrix_sync(fah[mi], Ah + r, PMK);
            wmma::load_matrix_sync(fal[mi], Al + r, PMK);
        }
#pragma unroll
        for (int ni = 0; ni < 2; ++ni) {
            int r = ks * 16 * PKN + wn * 32 + ni * 16;
            wmma::load_matrix_sync(fbh[ni], Bh + r, PKN);
            wmma::load_matrix_sync(fbl[ni], Bl + r, PKN);
        }
#pragma unroll
        for (int mi = 0; mi < 2; ++mi)
#pragma unroll
            for (int ni = 0; ni < 2; ++ni)
                MMA3(acc[mi][ni], fah[mi], fal[mi], fbh[ni], fbl[ni]);
    }
}

// MODE 2 (b_tilde = P^T.a): A col-major (tile [k][m]), B row-major (tile [k][n])
__device__ __forceinline__ void compute_B(const char* st, FragC acc[2][2], int wm, int wn) {
    const __nv_bfloat16* Ah = (const __nv_bfloat16*)(st);
    const __nv_bfloat16* Al = (const __nv_bfloat16*)(st + 8704);
    const __nv_bfloat16* Bh = (const __nv_bfloat16*)(st + 17408);
    const __nv_bfloat16* Bl = (const __nv_bfloat16*)(st + 26112);
#pragma unroll
    for (int ks = 0; ks < 2; ++ks) {
        wmma::fragment<wmma::matrix_a, 16, 16, 16, __nv_bfloat16, wmma::col_major> fah[2], fal[2];
        wmma::fragment<wmma::matrix_b, 16, 16, 16, __nv_bfloat16, wmma::row_major> fbh[2], fbl[2];
#pragma unroll
        for (int mi = 0; mi < 2; ++mi) {
            int r = ks * 16 * PKN + wm * 32 + mi * 16;
            wmma::load_matrix_sync(fah[mi], Ah + r, PKN);
            wmma::load_matrix_sync(fal[mi], Al + r, PKN);
        }
#pragma unroll
        for (int ni = 0; ni < 2; ++ni) {
            int r = ks * 16 * PKN + wn * 32 + ni * 16;
            wmma::load_matrix_sync(fbh[ni], Bh + r, PKN);
            wmma::load_matrix_sync(fbl[ni], Bl + r, PKN);
        }
#pragma unroll
        for (int mi = 0; mi < 2; ++mi)
#pragma unroll
            for (int ni = 0; ni < 2; ++ni)
                MMA3(acc[mi][ni], fah[mi], fal[mi], fbh[ni], fbl[ni]);
    }
}

// ---------------------------------------------------------------------------
// Generic GEMM kernel. MODE: 0=E, 1=a_tilde+m_a, 2=b_tilde+m_b
// Block tile 128x128, 512 threads, cp.async 3-deep raw pipeline +
// double-buffered split-bf16 stages.
// ---------------------------------------------------------------------------
template <int MODE>
__global__ __launch_bounds__(NT)
void k_gemm(const float* __restrict__ a, const float* __restrict__ bm,
            float* __restrict__ out) {
    constexpr int STAGE = (MODE == 0) ? 40960 : (MODE == 1) ? 37888 : 34816;
    extern __shared__ char sm[];
    char* rawb = sm;                       // RAWS x 32KB fp32 stages
    char* bst  = sm + BST_OFF;             // 2 x STAGE split-bf16 stages
    float* rs  = (float*)(sm + BST_OFF + 2 * STAGE);
    float* ri  = rs + 128;
    uint32_t raw_u = (uint32_t)__cvta_generic_to_shared(rawb);

    int t = threadIdx.x, wid = t >> 5;
    int wm = wid & 3, wn = wid >> 2;
    int bb = blockIdx.z, m0 = blockIdx.y * 128, n0 = blockIdx.x * 128;
    const size_t SS = (size_t)S * S;

    if (MODE == 1) {
        if (t < 128) { rs[t] = g_rmax[bb * S + m0 + t]; ri[t] = g_rinv[bb * S + m0 + t]; }
    } else if (MODE == 2) {
        if (t < 128) { rs[t] = g_cmax[bb * S + m0 + t]; ri[t] = g_cinv[bb * S + m0 + t]; }
    }

    const float* srcA;
    const float* srcB;
    if (MODE == 0) { srcA = a + bb * SS + (size_t)m0 * S;   srcB = bm + bb * SS + (size_t)n0 * S; }
    if (MODE == 1) { srcA = g_E + bb * SS + (size_t)m0 * S; srcB = bm + bb * SS + n0; }
    if (MODE == 2) { srcA = g_E + bb * SS + m0;             srcB = a + bb * SS + n0; }

#define CP_STAGE(c) do { uint32_t ru_ = raw_u + ((c) % RAWS) * RAW_BYTES;       \
        if (MODE == 2) cp_kn(srcA + (size_t)(c) * 32 * S, ru_, t);              \
        else           cp_mk(srcA + (c) * 32, ru_, t);                          \
        if (MODE == 0) cp_mk(srcB + (c) * 32, ru_ + 16384, t);                  \
        else           cp_kn(srcB + (size_t)(c) * 32 * S, ru_ + 16384, t);      \
        CP_COMMIT(); } while (0)

#define CONVERT(c) do { const char* ra_ = rawb + ((c) % RAWS) * RAW_BYTES;      \
        char* st_ = bst + ((c) & 1) * STAGE;                                    \
        if (MODE == 0)      cv_mk(ra_, st_, st_ + 10240, t);                    \
        else if (MODE == 1) cv_mk_soft(ra_, st_, st_ + 10240, t, rs, ri);       \
        else                cv_kn_soft(ra_, st_, st_ + 8704, t, rs, ri);        \
        if (MODE == 0)      cv_mk(ra_ + 16384, st_ + 20480, st_ + 30720, t);    \
        else if (MODE == 1) cv_kn(ra_ + 16384, st_ + 20480, st_ + 29184, t);    \
        else                cv_kn(ra_ + 16384, st_ + 17408, st_ + 26112, t);    \
        } while (0)

    FragC acc[2][2];
#pragma unroll
    for (int mi = 0; mi < 2; ++mi)
#pragma unroll
        for (int ni = 0; ni < 2; ++ni) wmma::fill_fragment(acc[mi][ni], 0.0f);

    // prologue: start chunks 0,1; convert 0 (self-synchronized per thread)
    CP_STAGE(0);
    CP_STAGE(1);
    CP_WAIT(1);                 // chunk 0 landed (this thread's chunks)
    __syncthreads();            // stats visible to all converters
    CONVERT(0);

#pragma unroll 1
    for (int c = 0; c < NC; ++c) {
        __syncthreads();        // bf16 stage (c&1) visible to all warps
        if (c + 2 < NC) { CP_STAGE(c + 2); CP_WAIT(1); }
        else            { CP_WAIT(0); }
        if (c + 1 < NC) CONVERT(c + 1);
        const char* stage = bst + (c & 1) * STAGE;
        if (MODE == 0)      compute_E(stage, acc, wm, wn);
        else if (MODE == 1) compute_A(stage, acc, wm, wn);
        else                compute_B(stage, acc, wm, wn);
    }
    __syncthreads();

    if (MODE == 0) {
        float* Eb = g_E + bb * SS + (size_t)m0 * S + n0;
#pragma unroll
        for (int mi = 0; mi < 2; ++mi)
#pragma unroll
            for (int ni = 0; ni < 2; ++ni)
                wmma::store_matrix_sync(Eb + (size_t)(wm * 32 + mi * 16) * S + wn * 32 + ni * 16,
                                        acc[mi][ni], S, wmma::mem_row_major);
        return;
    }

    // modes 1/2: stage result through smem, fused 4-way concat epilogue
    float* fs = (float*)sm;   // [128][PFS], reuses dead raw region
#pragma unroll
    for (int mi = 0; mi < 2; ++mi)
#pragma unroll
        for (int ni = 0; ni < 2; ++ni)
            wmma::store_matrix_sync(fs + (size_t)(wm * 32 + mi * 16) * PFS + wn * 32 + ni * 16,
                                    acc[mi][ni], PFS, wmma::mem_row_major);
    __syncthreads();

    const float* base = (MODE == 1) ? (a + ((size_t)bb * S + m0) * S + n0)
                                    : (bm + ((size_t)bb * S + m0) * S + n0);
    size_t obase = ((size_t)bb * S + m0) * 2048 + n0;
    if (MODE == 2) obase += (size_t)NB * S * 2048;
    float* ob = out + obase;
#pragma unroll
    for (int p = 0; p < 8; ++p) {
        int idx = t + p * NT;
        int r = idx >> 5, d4 = idx & 31;
        float4 xv = *(const float4*)(base + (size_t)r * S + 4 * d4);
        float4 tv = *(const float4*)(fs + (size_t)r * PFS + 4 * d4);
        float* o = ob + (size_t)r * 2048 + 4 * d4;
        *(float4*)(o)        = xv;
        *(float4*)(o + 512)  = tv;
        *(float4*)(o + 1024) = make_float4(xv.x - tv.x, xv.y - tv.y, xv.z - tv.z, xv.w - tv.w);
        *(float4*)(o + 1536) = make_float4(xv.x * tv.x, xv.y * tv.y, xv.z * tv.z, xv.w * tv.w);
    }
#undef CP_STAGE
#undef CONVERT
}

// ---------------------------------------------------------------------------
// Row softmax stats: one warp per row
// ---------------------------------------------------------------------------
__global__ __launch_bounds__(256)
void k_row_stats() {
    int wid = threadIdx.x >> 5, lane = threadIdx.x & 31;
    size_t row = (size_t)blockIdx.x * 8 + wid;
    const float* e = g_E + row * S;
    float4 v[4];
#pragma unroll
    for (int p = 0; p < 4; ++p) v[p] = *(const float4*)(e + lane * 4 + p * 128);
    float m = -3.402823466e38f;
#pragma unroll
    for (int p = 0; p < 4; ++p)
        m = fmaxf(m, fmaxf(fmaxf(v[p].x, v[p].y), fmaxf(v[p].z, v[p].w)));
#pragma unroll
    for (int o = 16; o; o >>= 1) m = fmaxf(m, __shfl_xor_sync(0xffffffffu, m, o));
    float s = 0.0f;
#pragma unroll
    for (int p = 0; p < 4; ++p)
        s += __expf(v[p].x - m) + __expf(v[p].y - m) + __expf(v[p].z - m) + __expf(v[p].w - m);
#pragma unroll
    for (int o = 16; o; o >>= 1) s += __shfl_xor_sync(0xffffffffu, s, o);
    if (lane == 0) { g_rmax[row] = m; g_rinv[row] = 1.0f / s; }
}

// ---------------------------------------------------------------------------
// Column softmax stats (over i), online. 64 cols x 4 row-slices per block.
// ---------------------------------------------------------------------------
__global__ __launch_bounds__(256)
void k_col_stats() {
    int b  = blockIdx.y;
    int j0 = blockIdx.x * 64;
    int c  = threadIdx.x & 63;
    int r  = threadIdx.x >> 6;
    int j  = j0 + c;
    const float* e = g_E + (size_t)b * S * S + j;
    float m = -3.402823466e38f, s = 0.0f;
    for (int i = r * 128; i < (r + 1) * 128; ++i) {
        float v  = e[(size_t)i * S];
        float nm = fmaxf(m, v);
        s = s * __expf(m - nm) + __expf(v - nm);
        m = nm;
    }
    __shared__ float sm2[4][64], ss2[4][64];
    sm2[r][c] = m; ss2[r][c] = s;
    __syncthreads();
    if (r == 0) {
        float M = m, Sv = s;
#pragma unroll
        for (int q = 1; q < 4; ++q) {
            float m2 = sm2[q][c], s2 = ss2[q][c];
            float nm = fmaxf(M, m2);
            Sv = Sv * __expf(M - nm) + s2 * __expf(m2 - nm);
            M = nm;
        }
        g_cmax[b * S + j] = M;
        g_cinv[b * S + j] = 1.0f / Sv;
    }
}

// ---------------------------------------------------------------------------

extern "C" void kernel_launch(void* const* d_in, const int* in_sizes, int n_in,
                              void* d_out, int out_size) {
    const float* a  = (const float*)d_in[0];
    const float* bm = (const float*)d_in[1];
    float* out = (float*)d_out;
    (void)in_sizes; (void)n_in; (void)out_size;

    const int SM0 = BST_OFF + 2 * 40960;
    const int SM1 = BST_OFF + 2 * 37888 + 1024;
    const int SM2 = BST_OFF + 2 * 34816 + 1024;

    static int configured = 0;
    if (!configured) {
        cudaFuncSetAttribute(k_gemm<0>, cudaFuncAttributeMaxDynamicSharedMemorySize, SM0);
        cudaFuncSetAttribute(k_gemm<1>, cudaFuncAttributeMaxDynamicSharedMemorySize, SM1);
        cudaFuncSetAttribute(k_gemm<2>, cudaFuncAttributeMaxDynamicSharedMemorySize, SM2);
        configured = 1;
    }

    dim3 gg(4, 4, NB);   // (n-tiles, m-tiles, batch)
    k_gemm<0><<<gg, NT, SM0>>>(a, bm, out);
    k_row_stats<<<NB * S / 8, 256>>>();
    k_col_stats<<<dim3(S / 64, NB), 256>>>();
    k_gemm<1><<<gg, NT, SM1>>>(a, bm, out);
    k_gemm<2><<<gg, NT, SM2>>>(a, bm, out);
}

// round 7
// speedup vs baseline: 1.8615x; 1.0232x over previous
#include <cuda_runtime.h>
#include <cuda_bf16.h>
#include <mma.h>
#include <cstdint>

using namespace nvcuda;

#define NB 32
#define S  512
#define NC 16            // K chunks of 32 (K=512)
#define NT 512           // threads per GEMM block
#define NSTG 4           // cp.async stages

// ---------------------------------------------------------------------------
// Device-global scratch (allocation-free per harness rules)
// ---------------------------------------------------------------------------
__device__ __align__(16) float g_E[(size_t)NB * S * S];   // 32 MB scores
__device__ float g_rmax[NB * S], g_rinv[NB * S];
__device__ float g_cmax[NB * S], g_cinv[NB * S];

#define BFARR(name) __device__ __align__(16) __nv_bfloat16 name[(size_t)NB * S * S]
BFARR(g_a_hi);  BFARR(g_a_lo);   // a  natural [b][i][d]
BFARR(g_b_hi);  BFARR(g_b_lo);   // b  natural [b][j][d]
BFARR(g_pa_hi); BFARR(g_pa_lo);  // row-softmax(E) natural [b][i][j]
BFARR(g_pb_hi); BFARR(g_pb_lo);  // col-softmax(E) natural [b][i][j]

// smem pitches (elements)
#define PMK 40     // [128 rows][k 32] bf16 tile, 80 B/row (LDSM conflict-free)
#define PKN 136    // [k 32][n 128] bf16 tile, 272 B/row
#define PFS 136    // [128][128] f32 epilogue staging

// ---------------------------------------------------------------------------
// cp.async helpers
// ---------------------------------------------------------------------------
__device__ __forceinline__ void cp16(uint32_t dst, const void* src) {
    asm volatile("cp.async.cg.shared.global [%0], [%1], 16;" :: "r"(dst), "l"(src));
}
#define CP_COMMIT() asm volatile("cp.async.commit_group;" ::: "memory")
#define CP_WAIT(n)  asm volatile("cp.async.wait_group %0;" :: "n"(n) : "memory")

// gmem bf16 rows -> smem tile. mk: 128 rows x 64B (pitch 80B). kn: 32 rows x 256B (pitch 272B).
__device__ __forceinline__ void cp_mk(const __nv_bfloat16* __restrict__ src, uint32_t du, int t) {
    int row = t >> 2, c = t & 3;
    cp16(du + row * 80 + c * 16, src + (size_t)row * S + c * 8);
}
__device__ __forceinline__ void cp_kn(const __nv_bfloat16* __restrict__ src, uint32_t du, int t) {
    int row = t >> 4, c = t & 15;
    cp16(du + row * 272 + c * 16, src + (size_t)row * S + c * 8);
}

// ---------------------------------------------------------------------------
// split helpers
// ---------------------------------------------------------------------------
__device__ __forceinline__ void split2(float x, unsigned short& h, unsigned short& l) {
    __nv_bfloat16 hb = __float2bfloat16(x);
    __nv_bfloat16 lb = __float2bfloat16(x - __bfloat162float(hb));
    h = __bfloat16_as_ushort(hb); l = __bfloat16_as_ushort(lb);
}
__device__ __forceinline__ void split4(float4 v, ushort4& h4, ushort4& l4) {
    split2(v.x, h4.x, l4.x); split2(v.y, h4.y, l4.y);
    split2(v.z, h4.z, l4.z); split2(v.w, h4.w, l4.w);
}

// ---------------------------------------------------------------------------
// K0: elementwise split a,b -> hi/lo bf16.  grid (8192, 2)
// ---------------------------------------------------------------------------
__global__ __launch_bounds__(256)
void k_split(const float* __restrict__ a, const float* __restrict__ bm) {
    const float* src = blockIdx.y ? bm : a;
    __nv_bfloat16* hi = blockIdx.y ? g_b_hi : g_a_hi;
    __nv_bfloat16* lo = blockIdx.y ? g_b_lo : g_a_lo;
    size_t i4 = (size_t)blockIdx.x * 256 + threadIdx.x;
    float4 v = ((const float4*)src)[i4];
    ushort4 h4, l4; split4(v, h4, l4);
    ((ushort4*)hi)[i4] = h4;
    ((ushort4*)lo)[i4] = l4;
}

// ---------------------------------------------------------------------------
// Row softmax stats: one warp per row
// ---------------------------------------------------------------------------
__global__ __launch_bounds__(256)
void k_row_stats() {
    int wid = threadIdx.x >> 5, lane = threadIdx.x & 31;
    size_t row = (size_t)blockIdx.x * 8 + wid;
    const float* e = g_E + row * S;
    float4 v[4];
#pragma unroll
    for (int p = 0; p < 4; ++p) v[p] = *(const float4*)(e + lane * 4 + p * 128);
    float m = -3.402823466e38f;
#pragma unroll
    for (int p = 0; p < 4; ++p)
        m = fmaxf(m, fmaxf(fmaxf(v[p].x, v[p].y), fmaxf(v[p].z, v[p].w)));
#pragma unroll
    for (int o = 16; o; o >>= 1) m = fmaxf(m, __shfl_xor_sync(0xffffffffu, m, o));
    float s = 0.0f;
#pragma unroll
    for (int p = 0; p < 4; ++p)
        s += __expf(v[p].x - m) + __expf(v[p].y - m) + __expf(v[p].z - m) + __expf(v[p].w - m);
#pragma unroll
    for (int o = 16; o; o >>= 1) s += __shfl_xor_sync(0xffffffffu, s, o);
    if (lane == 0) { g_rmax[row] = m; g_rinv[row] = 1.0f / s; }
}

// ---------------------------------------------------------------------------
// Column softmax stats (over i)
// ---------------------------------------------------------------------------
__global__ __launch_bounds__(256)
void k_col_stats() {
    int b  = blockIdx.y;
    int j0 = blockIdx.x * 64;
    int c  = threadIdx.x & 63;
    int r  = threadIdx.x >> 6;
    int j  = j0 + c;
    const float* e = g_E + (size_t)b * S * S + j;
    float m = -3.402823466e38f, s = 0.0f;
    for (int i = r * 128; i < (r + 1) * 128; ++i) {
        float v  = e[(size_t)i * S];
        float nm = fmaxf(m, v);
        s = s * __expf(m - nm) + __expf(v - nm);
        m = nm;
    }
    __shared__ float sm2[4][64], ss2[4][64];
    sm2[r][c] = m; ss2[r][c] = s;
    __syncthreads();
    if (r == 0) {
        float M = m, Sv = s;
#pragma unroll
        for (int q = 1; q < 4; ++q) {
            float m2 = sm2[q][c], s2 = ss2[q][c];
            float nm = fmaxf(M, m2);
            Sv = Sv * __expf(M - nm) + s2 * __expf(m2 - nm);
            M = nm;
        }
        g_cmax[b * S + j] = M;
        g_cinv[b * S + j] = 1.0f / Sv;
    }
}

// ---------------------------------------------------------------------------
// K_pmat: one pass over E -> PA hi/lo (row softmax), PB hi/lo (col softmax).
// grid (64 row-slabs, NB), 256 threads; 8 rows per block, 16 el per thread.
// ---------------------------------------------------------------------------
__global__ __launch_bounds__(256)
void k_pmat() {
    __shared__ float cm[S], ci[S];
    int b = blockIdx.y, r0 = blockIdx.x * 8;
    int t = threadIdx.x;
    for (int idx = t; idx < S; idx += 256) {
        cm[idx] = g_cmax[b * S + idx];
        ci[idx] = g_cinv[b * S + idx];
    }
    __syncthreads();
    int row = r0 + (t >> 5);
    int jb  = (t & 31) * 16;
    size_t base = (size_t)b * S * S + (size_t)row * S + jb;
    float rm = g_rmax[b * S + row], rv = g_rinv[b * S + row];
#pragma unroll
    for (int q = 0; q < 4; ++q) {
        float4 v = *(const float4*)(g_E + base + q * 4);
        int j = jb + q * 4;
        float4 pa = make_float4(__expf(v.x - rm) * rv, __expf(v.y - rm) * rv,
                                __expf(v.z - rm) * rv, __expf(v.w - rm) * rv);
        float4 pb = make_float4(__expf(v.x - cm[j]) * ci[j],
                                __expf(v.y - cm[j + 1]) * ci[j + 1],
                                __expf(v.z - cm[j + 2]) * ci[j + 2],
                                __expf(v.w - cm[j + 3]) * ci[j + 3]);
        ushort4 h4, l4;
        split4(pa, h4, l4);
        *(ushort4*)(g_pa_hi + base + q * 4) = h4;
        *(ushort4*)(g_pa_lo + base + q * 4) = l4;
        split4(pb, h4, l4);
        *(ushort4*)(g_pb_hi + base + q * 4) = h4;
        *(ushort4*)(g_pb_lo + base + q * 4) = l4;
    }
}

// ---------------------------------------------------------------------------
// wmma compute cores (16 warps, warp tile 32m x 32n; acc[2][2])
// ---------------------------------------------------------------------------
typedef wmma::fragment<wmma::accumulator, 16, 16, 16, float> FragC;

#define MMA3(acc, ah, al, bh, bl) do {            \
    wmma::mma_sync(acc, ah, bh, acc);             \
    wmma::mma_sync(acc, ah, bl, acc);             \
    wmma::mma_sync(acc, al, bh, acc); } while (0)

// MODE 0 (E = a.b^T): A row-major mk, B col-major (tile stored [n][k])
__device__ __forceinline__ void compute_E(const char* st, FragC acc[2][2], int wm, int wn) {
    const __nv_bfloat16* Ah = (const __nv_bfloat16*)(st);
    const __nv_bfloat16* Al = (const __nv_bfloat16*)(st + 10240);
    const __nv_bfloat16* Bh = (const __nv_bfloat16*)(st + 20480);
    const __nv_bfloat16* Bl = (const __nv_bfloat16*)(st + 30720);
#pragma unroll
    for (int ks = 0; ks < 2; ++ks) {
        wmma::fragment<wmma::matrix_a, 16, 16, 16, __nv_bfloat16, wmma::row_major> fah[2], fal[2];
        wmma::fragment<wmma::matrix_b, 16, 16, 16, __nv_bfloat16, wmma::col_major> fbh[2], fbl[2];
#pragma unroll
        for (int mi = 0; mi < 2; ++mi) {
            int r = (wm * 32 + mi * 16) * PMK + ks * 16;
            wmma::load_matrix_sync(fah[mi], Ah + r, PMK);
            wmma::load_matrix_sync(fal[mi], Al + r, PMK);
        }
#pragma unroll
        for (int ni = 0; ni < 2; ++ni) {
            int r = (wn * 32 + ni * 16) * PMK + ks * 16;
            wmma::load_matrix_sync(fbh[ni], Bh + r, PMK);
            wmma::load_matrix_sync(fbl[ni], Bl + r, PMK);
        }
#pragma unroll
        for (int mi = 0; mi < 2; ++mi)
#pragma unroll
            for (int ni = 0; ni < 2; ++ni)
                MMA3(acc[mi][ni], fah[mi], fal[mi], fbh[ni], fbl[ni]);
    }
}

// MODE 1 (a_tilde = PA.b): A row-major mk, B row-major kn
__device__ __forceinline__ void compute_A(const char* st, FragC acc[2][2], int wm, int wn) {
    const __nv_bfloat16* Ah = (const __nv_bfloat16*)(st);
    const __nv_bfloat16* Al = (const __nv_bfloat16*)(st + 10240);
    const __nv_bfloat16* Bh = (const __nv_bfloat16*)(st + 20480);
    const __nv_bfloat16* Bl = (const __nv_bfloat16*)(st + 29184);
#pragma unroll
    for (int ks = 0; ks < 2; ++ks) {
        wmma::fragment<wmma::matrix_a, 16, 16, 16, __nv_bfloat16, wmma::row_major> fah[2], fal[2];
        wmma::fragment<wmma::matrix_b, 16, 16, 16, __nv_bfloat16, wmma::row_major> fbh[2], fbl[2];
#pragma unroll
        for (int mi = 0; mi < 2; ++mi) {
            int r = (wm * 32 + mi * 16) * PMK + ks * 16;
            wmma::load_matrix_sync(fah[mi], Ah + r, PMK);
            wmma::load_matrix_sync(fal[mi], Al + r, PMK);
        }
#pragma unroll
        for (int ni = 0; ni < 2; ++ni) {
            int r = ks * 16 * PKN + wn * 32 + ni * 16;
            wmma::load_matrix_sync(fbh[ni], Bh + r, PKN);
            wmma::load_matrix_sync(fbl[ni], Bl + r, PKN);
        }
#pragma unroll
        for (int mi = 0; mi < 2; ++mi)
#pragma unroll
            for (int ni = 0; ni < 2; ++ni)
                MMA3(acc[mi][ni], fah[mi], fal[mi], fbh[ni], fbl[ni]);
    }
}

// MODE 2 (b_tilde = PB^T.a): A col-major (tile [k][m] = PB natural rows), B row-major kn
__device__ __forceinline__ void compute_B(const char* st, FragC acc[2][2], int wm, int wn) {
    const __nv_bfloat16* Ah = (const __nv_bfloat16*)(st);
    const __nv_bfloat16* Al = (const __nv_bfloat16*)(st + 8704);
    const __nv_bfloat16* Bh = (const __nv_bfloat16*)(st + 17408);
    const __nv_bfloat16* Bl = (const __nv_bfloat16*)(st + 26112);
#pragma unroll
    for (int ks = 0; ks < 2; ++ks) {
        wmma::fragment<wmma::matrix_a, 16, 16, 16, __nv_bfloat16, wmma::col_major> fah[2], fal[2];
        wmma::fragment<wmma::matrix_b, 16, 16, 16, __nv_bfloat16, wmma::row_major> fbh[2], fbl[2];
#pragma unroll
        for (int mi = 0; mi < 2; ++mi) {
            int r = ks * 16 * PKN + wm * 32 + mi * 16;
            wmma::load_matrix_sync(fah[mi], Ah + r, PKN);
            wmma::load_matrix_sync(fal[mi], Al + r, PKN);
        }
#pragma unroll
        for (int ni = 0; ni < 2; ++ni) {
            int r = ks * 16 * PKN + wn * 32 + ni * 16;
            wmma::load_matrix_sync(fbh[ni], Bh + r, PKN);
            wmma::load_matrix_sync(fbl[ni], Bl + r, PKN);
        }
#pragma unroll
        for (int mi = 0; mi < 2; ++mi)
#pragma unroll
            for (int ni = 0; ni < 2; ++ni)
                MMA3(acc[mi][ni], fah[mi], fal[mi], fbh[ni], fbl[ni]);
    }
}

// ---------------------------------------------------------------------------
// Pure-MMA GEMM kernel. MODE: 0=E, 1=a_tilde+m_a, 2=b_tilde+m_b
// Block tile 128x128, 512 threads, 4-stage cp.async bf16 pipeline.
// ---------------------------------------------------------------------------
template <int MODE>
__global__ __launch_bounds__(NT)
void k_gemm(const float* __restrict__ a, const float* __restrict__ bm,
            float* __restrict__ out) {
    constexpr int STAGE = (MODE == 0) ? 40960 : (MODE == 1) ? 37888 : 34816;
    extern __shared__ char sm[];
    uint32_t su = (uint32_t)__cvta_generic_to_shared(sm);

    int t = threadIdx.x, wid = t >> 5;
    int wm = wid & 3, wn = wid >> 2;
    int bb = blockIdx.z, m0 = blockIdx.y * 128, n0 = blockIdx.x * 128;
    const size_t SS = (size_t)S * S;
    const size_t bo = (size_t)bb * SS;

    // operand sources (bf16, natural rows)
    const __nv_bfloat16 *Ah, *Al, *Bh, *Bl;
    if (MODE == 0) { Ah = g_a_hi + bo + (size_t)m0 * S; Al = g_a_lo + bo + (size_t)m0 * S;
                     Bh = g_b_hi + bo + (size_t)n0 * S; Bl = g_b_lo + bo + (size_t)n0 * S; }
    if (MODE == 1) { Ah = g_pa_hi + bo + (size_t)m0 * S; Al = g_pa_lo + bo + (size_t)m0 * S;
                     Bh = g_b_hi + bo + n0;              Bl = g_b_lo + bo + n0; }
    if (MODE == 2) { Ah = g_pb_hi + bo + m0;             Al = g_pb_lo + bo + m0;
                     Bh = g_a_hi + bo + n0;              Bl = g_a_lo + bo + n0; }

#define CPSTAGE(c) do {                                                          \
        uint32_t stu_ = su + ((c) & 3) * STAGE;                                  \
        if (MODE == 2) { cp_kn(Ah + (size_t)(c) * 32 * S, stu_, t);              \
                         cp_kn(Al + (size_t)(c) * 32 * S, stu_ + 8704, t); }     \
        else           { cp_mk(Ah + (c) * 32, stu_, t);                          \
                         cp_mk(Al + (c) * 32, stu_ + 10240, t); }                \
        if (MODE == 0) { cp_mk(Bh + (c) * 32, stu_ + 20480, t);                  \
                         cp_mk(Bl + (c) * 32, stu_ + 30720, t); }                \
        else if (MODE == 1) { cp_kn(Bh + (size_t)(c) * 32 * S, stu_ + 20480, t); \
                              cp_kn(Bl + (size_t)(c) * 32 * S, stu_ + 29184, t);}\
        else           { cp_kn(Bh + (size_t)(c) * 32 * S, stu_ + 17408, t);      \
                         cp_kn(Bl + (size_t)(c) * 32 * S, stu_ + 26112, t); }    \
        CP_COMMIT(); } while (0)

    FragC acc[2][2];
#pragma unroll
    for (int mi = 0; mi < 2; ++mi)
#pragma unroll
        for (int ni = 0; ni < 2; ++ni) wmma::fill_fragment(acc[mi][ni], 0.0f);

    CPSTAGE(0); CPSTAGE(1); CPSTAGE(2);

#pragma unroll 1
    for (int c = 0; c < NC; ++c) {
        CP_WAIT(2);
        __syncthreads();
        if (c + 3 < NC) CPSTAGE(c + 3); else CP_COMMIT();
        const char* stage = sm + (c & 3) * STAGE;
        if (MODE == 0)      compute_E(stage, acc, wm, wn);
        else if (MODE == 1) compute_A(stage, acc, wm, wn);
        else                compute_B(stage, acc, wm, wn);
    }
    __syncthreads();

    if (MODE == 0) {
        float* Eb = g_E + bo + (size_t)m0 * S + n0;
#pragma unroll
        for (int mi = 0; mi < 2; ++mi)
#pragma unroll
            for (int ni = 0; ni < 2; ++ni)
                wmma::store_matrix_sync(Eb + (size_t)(wm * 32 + mi * 16) * S + wn * 32 + ni * 16,
                                        acc[mi][ni], S, wmma::mem_row_major);
        return;
    }

    // fused 4-way concat epilogue through smem staging
    float* fs = (float*)sm;
#pragma unroll
    for (int mi = 0; mi < 2; ++mi)
#pragma unroll
        for (int ni = 0; ni < 2; ++ni)
            wmma::store_matrix_sync(fs + (size_t)(wm * 32 + mi * 16) * PFS + wn * 32 + ni * 16,
                                    acc[mi][ni], PFS, wmma::mem_row_major);
    __syncthreads();

    const float* base = (MODE == 1) ? (a + ((size_t)bb * S + m0) * S + n0)
                                    : (bm + ((size_t)bb * S + m0) * S + n0);
    size_t obase = ((size_t)bb * S + m0) * 2048 + n0;
    if (MODE == 2) obase += (size_t)NB * S * 2048;
    float* ob = out + obase;
#pragma unroll
    for (int p = 0; p < 8; ++p) {
        int idx = t + p * NT;
        int r = idx >> 5, d4 = idx & 31;
        float4 xv = *(const float4*)(base + (size_t)r * S + 4 * d4);
        float4 tv = *(const float4*)(fs + (size_t)r * PFS + 4 * d4);
        float* o = ob + (size_t)r * 2048 + 4 * d4;
        *(float4*)(o)        = xv;
        *(float4*)(o + 512)  = tv;
        *(float4*)(o + 1024) = make_float4(xv.x - tv.x, xv.y - tv.y, xv.z - tv.z, xv.w - tv.w);
        *(float4*)(o + 1536) = make_float4(xv.x * tv.x, xv.y * tv.y, xv.z * tv.z, xv.w * tv.w);
    }
#undef CPSTAGE
}

// ---------------------------------------------------------------------------

extern "C" void kernel_launch(void* const* d_in, const int* in_sizes, int n_in,
                              void* d_out, int out_size) {
    const float* a  = (const float*)d_in[0];
    const float* bm = (const float*)d_in[1];
    float* out = (float*)d_out;
    (void)in_sizes; (void)n_in; (void)out_size;

    const int SM0 = NSTG * 40960;
    const int SM1 = NSTG * 37888;
    const int SM2 = NSTG * 34816;

    static int configured = 0;
    if (!configured) {
        cudaFuncSetAttribute(k_gemm<0>, cudaFuncAttributeMaxDynamicSharedMemorySize, SM0);
        cudaFuncSetAttribute(k_gemm<1>, cudaFuncAttributeMaxDynamicSharedMemorySize, SM1);
        cudaFuncSetAttribute(k_gemm<2>, cudaFuncAttributeMaxDynamicSharedMemorySize, SM2);
        configured = 1;
    }

    dim3 gg(4, 4, NB);   // (n-tiles, m-tiles, batch)
    k_split<<<dim3(8192, 2), 256>>>(a, bm);
    k_gemm<0><<<gg, NT, SM0>>>(a, bm, out);
    k_row_stats<<<NB * S / 8, 256>>>();
    k_col_stats<<<dim3(S / 64, NB), 256>>>();
    k_pmat<<<dim3(S / 8, NB), 256>>>();
    k_gemm<1><<<gg, NT, SM1>>>(a, bm, out);
    k_gemm<2><<<gg, NT, SM2>>>(a, bm, out);
}

// round 8
// speedup vs baseline: 1.8818x; 1.0109x over previous
#include <cuda_runtime.h>
#include <cuda_bf16.h>
#include <mma.h>
#include <cstdint>

using namespace nvcuda;

#define NB 32
#define S  512
#define NC 16            // K chunks of 32 (K=512)
#define NT 512           // threads per GEMM block
#define NSTG 4           // cp.async stages

// ---------------------------------------------------------------------------
// Device-global scratch (allocation-free per harness rules)
// ---------------------------------------------------------------------------
__device__ __align__(16) float g_E[(size_t)NB * S * S];   // 32 MB scores
__device__ float g_rmax[NB * S], g_rinv[NB * S];
__device__ float g_cmax[NB * S], g_cinv[NB * S];

#define BFARR(name) __device__ __align__(16) __nv_bfloat16 name[(size_t)NB * S * S]
BFARR(g_a_hi);  BFARR(g_a_lo);   // a  natural [b][i][d]
BFARR(g_b_hi);  BFARR(g_b_lo);   // b  natural [b][j][d]
BFARR(g_pa_hi); BFARR(g_pa_lo);  // row-softmax(E) natural [b][i][j]
BFARR(g_pb_hi); BFARR(g_pb_lo);  // col-softmax(E) natural [b][i][j]

// smem pitches (elements)
#define PMK 40     // [128 rows][k 32] bf16 tile, 80 B/row (LDSM conflict-free)
#define PKN 136    // [k 32][n 128] bf16 tile, 272 B/row
#define PFS 136    // [128][128] f32 epilogue staging

// ---------------------------------------------------------------------------
// cp.async helpers
// ---------------------------------------------------------------------------
__device__ __forceinline__ void cp16(uint32_t dst, const void* src) {
    asm volatile("cp.async.cg.shared.global [%0], [%1], 16;" :: "r"(dst), "l"(src));
}
#define CP_COMMIT() asm volatile("cp.async.commit_group;" ::: "memory")
#define CP_WAIT(n)  asm volatile("cp.async.wait_group %0;" :: "n"(n) : "memory")

// gmem bf16 rows -> smem tile. mk: 128 rows x 64B (pitch 80B). kn: 32 rows x 256B (pitch 272B).
__device__ __forceinline__ void cp_mk(const __nv_bfloat16* __restrict__ src, uint32_t du, int t) {
    int row = t >> 2, c = t & 3;
    cp16(du + row * 80 + c * 16, src + (size_t)row * S + c * 8);
}
__device__ __forceinline__ void cp_kn(const __nv_bfloat16* __restrict__ src, uint32_t du, int t) {
    int row = t >> 4, c = t & 15;
    cp16(du + row * 272 + c * 16, src + (size_t)row * S + c * 8);
}

// ---------------------------------------------------------------------------
// split helpers
// ---------------------------------------------------------------------------
__device__ __forceinline__ void split2(float x, unsigned short& h, unsigned short& l) {
    __nv_bfloat16 hb = __float2bfloat16(x);
    __nv_bfloat16 lb = __float2bfloat16(x - __bfloat162float(hb));
    h = __bfloat16_as_ushort(hb); l = __bfloat16_as_ushort(lb);
}
__device__ __forceinline__ void split4(float4 v, ushort4& h4, ushort4& l4) {
    split2(v.x, h4.x, l4.x); split2(v.y, h4.y, l4.y);
    split2(v.z, h4.z, l4.z); split2(v.w, h4.w, l4.w);
}

// ---------------------------------------------------------------------------
// K0: elementwise split a,b -> hi/lo bf16.  grid (8192, 2)
// ---------------------------------------------------------------------------
__global__ __launch_bounds__(256)
void k_split(const float* __restrict__ a, const float* __restrict__ bm) {
    const float* src = blockIdx.y ? bm : a;
    __nv_bfloat16* hi = blockIdx.y ? g_b_hi : g_a_hi;
    __nv_bfloat16* lo = blockIdx.y ? g_b_lo : g_a_lo;
    size_t i4 = (size_t)blockIdx.x * 256 + threadIdx.x;
    float4 v = ((const float4*)src)[i4];
    ushort4 h4, l4; split4(v, h4, l4);
    ((ushort4*)hi)[i4] = h4;
    ((ushort4*)lo)[i4] = l4;
}

// ---------------------------------------------------------------------------
// Row softmax stats: one warp per row
// ---------------------------------------------------------------------------
__global__ __launch_bounds__(256)
void k_row_stats() {
    int wid = threadIdx.x >> 5, lane = threadIdx.x & 31;
    size_t row = (size_t)blockIdx.x * 8 + wid;
    const float* e = g_E + row * S;
    float4 v[4];
#pragma unroll
    for (int p = 0; p < 4; ++p) v[p] = *(const float4*)(e + lane * 4 + p * 128);
    float m = -3.402823466e38f;
#pragma unroll
    for (int p = 0; p < 4; ++p)
        m = fmaxf(m, fmaxf(fmaxf(v[p].x, v[p].y), fmaxf(v[p].z, v[p].w)));
#pragma unroll
    for (int o = 16; o; o >>= 1) m = fmaxf(m, __shfl_xor_sync(0xffffffffu, m, o));
    float s = 0.0f;
#pragma unroll
    for (int p = 0; p < 4; ++p)
        s += __expf(v[p].x - m) + __expf(v[p].y - m) + __expf(v[p].z - m) + __expf(v[p].w - m);
#pragma unroll
    for (int o = 16; o; o >>= 1) s += __shfl_xor_sync(0xffffffffu, s, o);
    if (lane == 0) { g_rmax[row] = m; g_rinv[row] = 1.0f / s; }
}

// ---------------------------------------------------------------------------
// Column softmax stats (over i)
// ---------------------------------------------------------------------------
__global__ __launch_bounds__(256)
void k_col_stats() {
    int b  = blockIdx.y;
    int j0 = blockIdx.x * 64;
    int c  = threadIdx.x & 63;
    int r  = threadIdx.x >> 6;
    int j  = j0 + c;
    const float* e = g_E + (size_t)b * S * S + j;
    float m = -3.402823466e38f, s = 0.0f;
    for (int i = r * 128; i < (r + 1) * 128; ++i) {
        float v  = e[(size_t)i * S];
        float nm = fmaxf(m, v);
        s = s * __expf(m - nm) + __expf(v - nm);
        m = nm;
    }
    __shared__ float sm2[4][64], ss2[4][64];
    sm2[r][c] = m; ss2[r][c] = s;
    __syncthreads();
    if (r == 0) {
        float M = m, Sv = s;
#pragma unroll
        for (int q = 1; q < 4; ++q) {
            float m2 = sm2[q][c], s2 = ss2[q][c];
            float nm = fmaxf(M, m2);
            Sv = Sv * __expf(M - nm) + s2 * __expf(m2 - nm);
            M = nm;
        }
        g_cmax[b * S + j] = M;
        g_cinv[b * S + j] = 1.0f / Sv;
    }
}

// ---------------------------------------------------------------------------
// K_pmat: one pass over E -> PA hi/lo (row softmax), PB hi/lo (col softmax).
// grid (64 row-slabs, NB), 256 threads; 8 rows per block, 16 el per thread.
// ---------------------------------------------------------------------------
__global__ __launch_bounds__(256)
void k_pmat() {
    __shared__ float cm[S], ci[S];
    int b = blockIdx.y, r0 = blockIdx.x * 8;
    int t = threadIdx.x;
    for (int idx = t; idx < S; idx += 256) {
        cm[idx] = g_cmax[b * S + idx];
        ci[idx] = g_cinv[b * S + idx];
    }
    __syncthreads();
    int row = r0 + (t >> 5);
    int jb  = (t & 31) * 16;
    size_t base = (size_t)b * S * S + (size_t)row * S + jb;
    float rm = g_rmax[b * S + row], rv = g_rinv[b * S + row];
#pragma unroll
    for (int q = 0; q < 4; ++q) {
        float4 v = *(const float4*)(g_E + base + q * 4);
        int j = jb + q * 4;
        float4 pa = make_float4(__expf(v.x - rm) * rv, __expf(v.y - rm) * rv,
                                __expf(v.z - rm) * rv, __expf(v.w - rm) * rv);
        float4 pb = make_float4(__expf(v.x - cm[j]) * ci[j],
                                __expf(v.y - cm[j + 1]) * ci[j + 1],
                                __expf(v.z - cm[j + 2]) * ci[j + 2],
                                __expf(v.w - cm[j + 3]) * ci[j + 3]);
        ushort4 h4, l4;
        split4(pa, h4, l4);
        *(ushort4*)(g_pa_hi + base + q * 4) = h4;
        *(ushort4*)(g_pa_lo + base + q * 4) = l4;
        split4(pb, h4, l4);
        *(ushort4*)(g_pb_hi + base + q * 4) = h4;
        *(ushort4*)(g_pb_lo + base + q * 4) = l4;
    }
}

// ---------------------------------------------------------------------------
// wmma compute cores (16 warps, warp tile 32m x 32n; acc[2][2])
// ---------------------------------------------------------------------------
typedef wmma::fragment<wmma::accumulator, 16, 16, 16, float> FragC;

#define MMA3(acc, ah, al, bh, bl) do {            \
    wmma::mma_sync(acc, ah, bh, acc);             \
    wmma::mma_sync(acc, ah, bl, acc);             \
    wmma::mma_sync(acc, al, bh, acc); } while (0)

// MODE 0 (E = a.b^T): A row-major mk, B col-major (tile stored [n][k])
__device__ __forceinline__ void compute_E(const char* st, FragC acc[2][2], int wm, int wn) {
    const __nv_bfloat16* Ah = (const __nv_bfloat16*)(st);
    const __nv_bfloat16* Al = (const __nv_bfloat16*)(st + 10240);
    const __nv_bfloat16* Bh = (const __nv_bfloat16*)(st + 20480);
    const __nv_bfloat16* Bl = (const __nv_bfloat16*)(st + 30720);
#pragma unroll
    for (int ks = 0; ks < 2; ++ks) {
        wmma::fragment<wmma::matrix_a, 16, 16, 16, __nv_bfloat16, wmma::row_major> fah[2], fal[2];
        wmma::fragment<wmma::matrix_b, 16, 16, 16, __nv_bfloat16, wmma::col_major> fbh[2], fbl[2];
#pragma unroll
        for (int mi = 0; mi < 2; ++mi) {
            int r = (wm * 32 + mi * 16) * PMK + ks * 16;
            wmma::load_matrix_sync(fah[mi], Ah + r, PMK);
            wmma::load_matrix_sync(fal[mi], Al + r, PMK);
        }
#pragma unroll
        for (int ni = 0; ni < 2; ++ni) {
            int r = (wn * 32 + ni * 16) * PMK + ks * 16;
            wmma::load_matrix_sync(fbh[ni], Bh + r, PMK);
            wmma::load_matrix_sync(fbl[ni], Bl + r, PMK);
        }
#pragma unroll
        for (int mi = 0; mi < 2; ++mi)
#pragma unroll
            for (int ni = 0; ni < 2; ++ni)
                MMA3(acc[mi][ni], fah[mi], fal[mi], fbh[ni], fbl[ni]);
    }
}

// MODE 1 (a_tilde = PA.b): A row-major mk, B row-major kn
__device__ __forceinline__ void compute_A(const char* st, FragC acc[2][2], int wm, int wn) {
    const __nv_bfloat16* Ah = (const __nv_bfloat16*)(st);
    const __nv_bfloat16* Al = (const __nv_bfloat16*)(st + 10240);
    const __nv_bfloat16* Bh = (const __nv_bfloat16*)(st + 20480);
    const __nv_bfloat16* Bl = (const __nv_bfloat16*)(st + 29184);
#pragma unroll
    for (int ks = 0; ks < 2; ++ks) {
        wmma::fragment<wmma::matrix_a, 16, 16, 16, __nv_bfloat16, wmma::row_major> fah[2], fal[2];
        wmma::fragment<wmma::matrix_b, 16, 16, 16, __nv_bfloat16, wmma::row_major> fbh[2], fbl[2];
#pragma unroll
        for (int mi = 0; mi < 2; ++mi) {
            int r = (wm * 32 + mi * 16) * PMK + ks * 16;
            wmma::load_matrix_sync(fah[mi], Ah + r, PMK);
            wmma::load_matrix_sync(fal[mi], Al + r, PMK);
        }
#pragma unroll
        for (int ni = 0; ni < 2; ++ni) {
            int r = ks * 16 * PKN + wn * 32 + ni * 16;
            wmma::load_matrix_sync(fbh[ni], Bh + r, PKN);
            wmma::load_matrix_sync(fbl[ni], Bl + r, PKN);
        }
#pragma unroll
        for (int mi = 0; mi < 2; ++mi)
#pragma unroll
            for (int ni = 0; ni < 2; ++ni)
                MMA3(acc[mi][ni], fah[mi], fal[mi], fbh[ni], fbl[ni]);
    }
}

// MODE 2 (b_tilde = PB^T.a): A col-major (tile [k][m] = PB natural rows), B row-major kn
__device__ __forceinline__ void compute_B(const char* st, FragC acc[2][2], int wm, int wn) {
    const __nv_bfloat16* Ah = (const __nv_bfloat16*)(st);
    const __nv_bfloat16* Al = (const __nv_bfloat16*)(st + 8704);
    const __nv_bfloat16* Bh = (const __nv_bfloat16*)(st + 17408);
    const __nv_bfloat16* Bl = (const __nv_bfloat16*)(st + 26112);
#pragma unroll
    for (int ks = 0; ks < 2; ++ks) {
        wmma::fragment<wmma::matrix_a, 16, 16, 16, __nv_bfloat16, wmma::col_major> fah[2], fal[2];
        wmma::fragment<wmma::matrix_b, 16, 16, 16, __nv_bfloat16, wmma::row_major> fbh[2], fbl[2];
#pragma unroll
        for (int mi = 0; mi < 2; ++mi) {
            int r = ks * 16 * PKN + wm * 32 + mi * 16;
            wmma::load_matrix_sync(fah[mi], Ah + r, PKN);
            wmma::load_matrix_sync(fal[mi], Al + r, PKN);
        }
#pragma unroll
        for (int ni = 0; ni < 2; ++ni) {
            int r = ks * 16 * PKN + wn * 32 + ni * 16;
            wmma::load_matrix_sync(fbh[ni], Bh + r, PKN);
            wmma::load_matrix_sync(fbl[ni], Bl + r, PKN);
        }
#pragma unroll
        for (int mi = 0; mi < 2; ++mi)
#pragma unroll
            for (int ni = 0; ni < 2; ++ni)
                MMA3(acc[mi][ni], fah[mi], fal[mi], fbh[ni], fbl[ni]);
    }
}

// ---------------------------------------------------------------------------
// Pure-MMA GEMM kernel. MODE: 0=E, 1=a_tilde+m_a, 2=b_tilde+m_b
// Block tile 128x128, 512 threads, 4-stage cp.async bf16 pipeline.
// ---------------------------------------------------------------------------
template <int MODE>
__global__ __launch_bounds__(NT)
void k_gemm(const float* __restrict__ a, const float* __restrict__ bm,
            float* __restrict__ out) {
    constexpr int STAGE = (MODE == 0) ? 40960 : (MODE == 1) ? 37888 : 34816;
    extern __shared__ char sm[];
    uint32_t su = (uint32_t)__cvta_generic_to_shared(sm);

    int t = threadIdx.x, wid = t >> 5;
    int wm = wid & 3, wn = wid >> 2;
    int bb = blockIdx.z, m0 = blockIdx.y * 128, n0 = blockIdx.x * 128;
    const size_t SS = (size_t)S * S;
    const size_t bo = (size_t)bb * SS;

    // operand sources (bf16, natural rows)
    const __nv_bfloat16 *Ah, *Al, *Bh, *Bl;
    if (MODE == 0) { Ah = g_a_hi + bo + (size_t)m0 * S; Al = g_a_lo + bo + (size_t)m0 * S;
                     Bh = g_b_hi + bo + (size_t)n0 * S; Bl = g_b_lo + bo + (size_t)n0 * S; }
    if (MODE == 1) { Ah = g_pa_hi + bo + (size_t)m0 * S; Al = g_pa_lo + bo + (size_t)m0 * S;
                     Bh = g_b_hi + bo + n0;              Bl = g_b_lo + bo + n0; }
    if (MODE == 2) { Ah = g_pb_hi + bo + m0;             Al = g_pb_lo + bo + m0;
                     Bh = g_a_hi + bo + n0;              Bl = g_a_lo + bo + n0; }

#define CPSTAGE(c) do {                                                          \
        uint32_t stu_ = su + ((c) & 3) * STAGE;                                  \
        if (MODE == 2) { cp_kn(Ah + (size_t)(c) * 32 * S, stu_, t);              \
                         cp_kn(Al + (size_t)(c) * 32 * S, stu_ + 8704, t); }     \
        else           { cp_mk(Ah + (c) * 32, stu_, t);                          \
                         cp_mk(Al + (c) * 32, stu_ + 10240, t); }                \
        if (MODE == 0) { cp_mk(Bh + (c) * 32, stu_ + 20480, t);                  \
                         cp_mk(Bl + (c) * 32, stu_ + 30720, t); }                \
        else if (MODE == 1) { cp_kn(Bh + (size_t)(c) * 32 * S, stu_ + 20480, t); \
                              cp_kn(Bl + (size_t)(c) * 32 * S, stu_ + 29184, t);}\
        else           { cp_kn(Bh + (size_t)(c) * 32 * S, stu_ + 17408, t);      \
                         cp_kn(Bl + (size_t)(c) * 32 * S, stu_ + 26112, t); }    \
        CP_COMMIT(); } while (0)

    FragC acc[2][2];
#pragma unroll
    for (int mi = 0; mi < 2; ++mi)
#pragma unroll
        for (int ni = 0; ni < 2; ++ni) wmma::fill_fragment(acc[mi][ni], 0.0f);

    CPSTAGE(0); CPSTAGE(1); CPSTAGE(2);

#pragma unroll 1
    for (int c = 0; c < NC; ++c) {
        CP_WAIT(2);
        __syncthreads();
        if (c + 3 < NC) CPSTAGE(c + 3); else CP_COMMIT();
        const char* stage = sm + (c & 3) * STAGE;
        if (MODE == 0)      compute_E(stage, acc, wm, wn);
        else if (MODE == 1) compute_A(stage, acc, wm, wn);
        else                compute_B(stage, acc, wm, wn);
    }
    __syncthreads();

    if (MODE == 0) {
        float* Eb = g_E + bo + (size_t)m0 * S + n0;
#pragma unroll
        for (int mi = 0; mi < 2; ++mi)
#pragma unroll
            for (int ni = 0; ni < 2; ++ni)
                wmma::store_matrix_sync(Eb + (size_t)(wm * 32 + mi * 16) * S + wn * 32 + ni * 16,
                                        acc[mi][ni], S, wmma::mem_row_major);
        return;
    }

    // fused 4-way concat epilogue through smem staging
    float* fs = (float*)sm;
#pragma unroll
    for (int mi = 0; mi < 2; ++mi)
#pragma unroll
        for (int ni = 0; ni < 2; ++ni)
            wmma::store_matrix_sync(fs + (size_t)(wm * 32 + mi * 16) * PFS + wn * 32 + ni * 16,
                                    acc[mi][ni], PFS, wmma::mem_row_major);
    __syncthreads();

    const float* base = (MODE == 1) ? (a + ((size_t)bb * S + m0) * S + n0)
                                    : (bm + ((size_t)bb * S + m0) * S + n0);
    size_t obase = ((size_t)bb * S + m0) * 2048 + n0;
    if (MODE == 2) obase += (size_t)NB * S * 2048;
    float* ob = out + obase;
#pragma unroll
    for (int p = 0; p < 8; ++p) {
        int idx = t + p * NT;
        int r = idx >> 5, d4 = idx & 31;
        float4 xv = *(const float4*)(base + (size_t)r * S + 4 * d4);
        float4 tv = *(const float4*)(fs + (size_t)r * PFS + 4 * d4);
        float* o = ob + (size_t)r * 2048 + 4 * d4;
        *(float4*)(o)        = xv;
        *(float4*)(o + 512)  = tv;
        *(float4*)(o + 1024) = make_float4(xv.x - tv.x, xv.y - tv.y, xv.z - tv.z, xv.w - tv.w);
        *(float4*)(o + 1536) = make_float4(xv.x * tv.x, xv.y * tv.y, xv.z * tv.z, xv.w * tv.w);
    }
#undef CPSTAGE
}

// ---------------------------------------------------------------------------

extern "C" void kernel_launch(void* const* d_in, const int* in_sizes, int n_in,
                              void* d_out, int out_size) {
    const float* a  = (const float*)d_in[0];
    const float* bm = (const float*)d_in[1];
    float* out = (float*)d_out;
    (void)in_sizes; (void)n_in; (void)out_size;

    const int SM0 = NSTG * 40960;
    const int SM1 = NSTG * 37888;
    const int SM2 = NSTG * 34816;

    static int configured = 0;
    if (!configured) {
        cudaFuncSetAttribute(k_gemm<0>, cudaFuncAttributeMaxDynamicSharedMemorySize, SM0);
        cudaFuncSetAttribute(k_gemm<1>, cudaFuncAttributeMaxDynamicSharedMemorySize, SM1);
        cudaFuncSetAttribute(k_gemm<2>, cudaFuncAttributeMaxDynamicSharedMemorySize, SM2);
        configured = 1;
    }

    dim3 gg(4, 4, NB);   // (n-tiles, m-tiles, batch)
    k_split<<<dim3(8192, 2), 256>>>(a, bm);
    k_gemm<0><<<gg, NT, SM0>>>(a, bm, out);
    k_row_stats<<<NB * S / 8, 256>>>();
    k_col_stats<<<dim3(S / 64, NB), 256>>>();
    k_pmat<<<dim3(S / 8, NB), 256>>>();
    k_gemm<1><<<gg, NT, SM1>>>(a, bm, out);
    k_gemm<2><<<gg, NT, SM2>>>(a, bm, out);
}

// round 9
// speedup vs baseline: 2.0218x; 1.0744x over previous
#include <cuda_runtime.h>
#include <cuda_bf16.h>
#include <mma.h>
#include <cstdint>

using namespace nvcuda;

#define NB 32
#define S  512
#define NC 16            // K chunks of 32 (K=512)
#define NT 512           // threads per GEMM block
#define NSTG 4           // cp.async stages

// ---------------------------------------------------------------------------
// Device-global scratch (allocation-free per harness rules)
// ---------------------------------------------------------------------------
__device__ __align__(16) float g_E[(size_t)NB * S * S];   // 32 MB scores
__device__ float g_rmax[NB * S], g_rinv[NB * S];
__device__ float g_cmax[NB * S], g_cinv[NB * S];

#define BFARR(name) __device__ __align__(16) __nv_bfloat16 name[(size_t)NB * S * S]
BFARR(g_a_hi);  BFARR(g_a_lo);   // a  natural [b][i][d]
BFARR(g_b_hi);  BFARR(g_b_lo);   // b  natural [b][j][d]
BFARR(g_pa_hi); BFARR(g_pa_lo);  // row-softmax(E) natural [b][i][j]
BFARR(g_pb_hi); BFARR(g_pb_lo);  // col-softmax(E) natural [b][i][j]

// smem pitches (elements)
#define PMK 40     // [128 rows][k 32] bf16 tile, 80 B/row (LDSM conflict-free)
#define PKN 136    // [k 32][n 128] bf16 tile, 272 B/row
#define PFS 136    // [128][128] f32 epilogue staging

// ---------------------------------------------------------------------------
// cp.async helpers
// ---------------------------------------------------------------------------
__device__ __forceinline__ void cp16(uint32_t dst, const void* src) {
    asm volatile("cp.async.cg.shared.global [%0], [%1], 16;" :: "r"(dst), "l"(src));
}
#define CP_COMMIT() asm volatile("cp.async.commit_group;" ::: "memory")
#define CP_WAIT(n)  asm volatile("cp.async.wait_group %0;" :: "n"(n) : "memory")

__device__ __forceinline__ void cp_mk(const __nv_bfloat16* __restrict__ src, uint32_t du, int t) {
    int row = t >> 2, c = t & 3;
    cp16(du + row * 80 + c * 16, src + (size_t)row * S + c * 8);
}
__device__ __forceinline__ void cp_kn(const __nv_bfloat16* __restrict__ src, uint32_t du, int t) {
    int row = t >> 4, c = t & 15;
    cp16(du + row * 272 + c * 16, src + (size_t)row * S + c * 8);
}

// ---------------------------------------------------------------------------
// split helpers
// ---------------------------------------------------------------------------
__device__ __forceinline__ void split2(float x, unsigned short& h, unsigned short& l) {
    __nv_bfloat16 hb = __float2bfloat16(x);
    __nv_bfloat16 lb = __float2bfloat16(x - __bfloat162float(hb));
    h = __bfloat16_as_ushort(hb); l = __bfloat16_as_ushort(lb);
}
__device__ __forceinline__ void split4(float4 v, ushort4& h4, ushort4& l4) {
    split2(v.x, h4.x, l4.x); split2(v.y, h4.y, l4.y);
    split2(v.z, h4.z, l4.z); split2(v.w, h4.w, l4.w);
}

// ---------------------------------------------------------------------------
// K0: elementwise split a,b -> hi/lo bf16.  grid (8192, 2)
// ---------------------------------------------------------------------------
__global__ __launch_bounds__(256)
void k_split(const float* __restrict__ a, const float* __restrict__ bm) {
    const float* src = blockIdx.y ? bm : a;
    __nv_bfloat16* hi = blockIdx.y ? g_b_hi : g_a_hi;
    __nv_bfloat16* lo = blockIdx.y ? g_b_lo : g_a_lo;
    size_t i4 = (size_t)blockIdx.x * 256 + threadIdx.x;
    float4 v = ((const float4*)src)[i4];
    ushort4 h4, l4; split4(v, h4, l4);
    ((ushort4*)hi)[i4] = h4;
    ((ushort4*)lo)[i4] = l4;
}

// ---------------------------------------------------------------------------
// Row softmax stats: one warp per row
// ---------------------------------------------------------------------------
__global__ __launch_bounds__(256)
void k_row_stats() {
    int wid = threadIdx.x >> 5, lane = threadIdx.x & 31;
    size_t row = (size_t)blockIdx.x * 8 + wid;
    const float* e = g_E + row * S;
    float4 v[4];
#pragma unroll
    for (int p = 0; p < 4; ++p) v[p] = *(const float4*)(e + lane * 4 + p * 128);
    float m = -3.402823466e38f;
#pragma unroll
    for (int p = 0; p < 4; ++p)
        m = fmaxf(m, fmaxf(fmaxf(v[p].x, v[p].y), fmaxf(v[p].z, v[p].w)));
#pragma unroll
    for (int o = 16; o; o >>= 1) m = fmaxf(m, __shfl_xor_sync(0xffffffffu, m, o));
    float s = 0.0f;
#pragma unroll
    for (int p = 0; p < 4; ++p)
        s += __expf(v[p].x - m) + __expf(v[p].y - m) + __expf(v[p].z - m) + __expf(v[p].w - m);
#pragma unroll
    for (int o = 16; o; o >>= 1) s += __shfl_xor_sync(0xffffffffu, s, o);
    if (lane == 0) { g_rmax[row] = m; g_rinv[row] = 1.0f / s; }
}

// ---------------------------------------------------------------------------
// Column softmax stats (over i)
// ---------------------------------------------------------------------------
__global__ __launch_bounds__(256)
void k_col_stats() {
    int b  = blockIdx.y;
    int j0 = blockIdx.x * 64;
    int c  = threadIdx.x & 63;
    int r  = threadIdx.x >> 6;
    int j  = j0 + c;
    const float* e = g_E + (size_t)b * S * S + j;
    float m = -3.402823466e38f, s = 0.0f;
    for (int i = r * 128; i < (r + 1) * 128; ++i) {
        float v  = e[(size_t)i * S];
        float nm = fmaxf(m, v);
        s = s * __expf(m - nm) + __expf(v - nm);
        m = nm;
    }
    __shared__ float sm2[4][64], ss2[4][64];
    sm2[r][c] = m; ss2[r][c] = s;
    __syncthreads();
    if (r == 0) {
        float M = m, Sv = s;
#pragma unroll
        for (int q = 1; q < 4; ++q) {
            float m2 = sm2[q][c], s2 = ss2[q][c];
            float nm = fmaxf(M, m2);
            Sv = Sv * __expf(M - nm) + s2 * __expf(m2 - nm);
            M = nm;
        }
        g_cmax[b * S + j] = M;
        g_cinv[b * S + j] = 1.0f / Sv;
    }
}

// ---------------------------------------------------------------------------
// K_pmat: one pass over E -> PA hi/lo (row softmax), PB hi/lo (col softmax).
// ---------------------------------------------------------------------------
__global__ __launch_bounds__(256)
void k_pmat() {
    __shared__ float cm[S], ci[S];
    int b = blockIdx.y, r0 = blockIdx.x * 8;
    int t = threadIdx.x;
    for (int idx = t; idx < S; idx += 256) {
        cm[idx] = g_cmax[b * S + idx];
        ci[idx] = g_cinv[b * S + idx];
    }
    __syncthreads();
    int row = r0 + (t >> 5);
    int jb  = (t & 31) * 16;
    size_t base = (size_t)b * S * S + (size_t)row * S + jb;
    float rm = g_rmax[b * S + row], rv = g_rinv[b * S + row];
#pragma unroll
    for (int q = 0; q < 4; ++q) {
        float4 v = *(const float4*)(g_E + base + q * 4);
        int j = jb + q * 4;
        float4 pa = make_float4(__expf(v.x - rm) * rv, __expf(v.y - rm) * rv,
                                __expf(v.z - rm) * rv, __expf(v.w - rm) * rv);
        float4 pb = make_float4(__expf(v.x - cm[j]) * ci[j],
                                __expf(v.y - cm[j + 1]) * ci[j + 1],
                                __expf(v.z - cm[j + 2]) * ci[j + 2],
                                __expf(v.w - cm[j + 3]) * ci[j + 3]);
        ushort4 h4, l4;
        split4(pa, h4, l4);
        *(ushort4*)(g_pa_hi + base + q * 4) = h4;
        *(ushort4*)(g_pa_lo + base + q * 4) = l4;
        split4(pb, h4, l4);
        *(ushort4*)(g_pb_hi + base + q * 4) = h4;
        *(ushort4*)(g_pb_lo + base + q * 4) = l4;
    }
}

// ---------------------------------------------------------------------------
// wmma compute cores. 16 warps, warp tile 32m x 32n; acc[2][2].
// TERM-MAJOR MMA ordering: all hh, then all hl, then all lh — same-acc reuse
// distance 4 (was 1) to hide HMMA latency within a warp.
// ---------------------------------------------------------------------------
typedef wmma::fragment<wmma::accumulator, 16, 16, 16, float> FragC;

#define TERM_MAJOR(acc, fah, fal, fbh, fbl) do {                                 \
    _Pragma("unroll")                                                            \
    for (int mi = 0; mi < 2; ++mi) { _Pragma("unroll")                           \
        for (int ni = 0; ni < 2; ++ni) wmma::mma_sync(acc[mi][ni], fah[mi], fbh[ni], acc[mi][ni]); } \
    _Pragma("unroll")                                                            \
    for (int mi = 0; mi < 2; ++mi) { _Pragma("unroll")                           \
        for (int ni = 0; ni < 2; ++ni) wmma::mma_sync(acc[mi][ni], fah[mi], fbl[ni], acc[mi][ni]); } \
    _Pragma("unroll")                                                            \
    for (int mi = 0; mi < 2; ++mi) { _Pragma("unroll")                           \
        for (int ni = 0; ni < 2; ++ni) wmma::mma_sync(acc[mi][ni], fal[mi], fbh[ni], acc[mi][ni]); } \
    } while (0)

// MODE 0 (E = a.b^T): A row-major mk, B col-major (tile stored [n][k])
__device__ __forceinline__ void compute_E(const char* st, FragC acc[2][2], int wm, int wn) {
    const __nv_bfloat16* Ah = (const __nv_bfloat16*)(st);
    const __nv_bfloat16* Al = (const __nv_bfloat16*)(st + 10240);
    const __nv_bfloat16* Bh = (const __nv_bfloat16*)(st + 20480);
    const __nv_bfloat16* Bl = (const __nv_bfloat16*)(st + 30720);
#pragma unroll
    for (int ks = 0; ks < 2; ++ks) {
        wmma::fragment<wmma::matrix_a, 16, 16, 16, __nv_bfloat16, wmma::row_major> fah[2], fal[2];
        wmma::fragment<wmma::matrix_b, 16, 16, 16, __nv_bfloat16, wmma::col_major> fbh[2], fbl[2];
#pragma unroll
        for (int mi = 0; mi < 2; ++mi) {
            int r = (wm * 32 + mi * 16) * PMK + ks * 16;
            wmma::load_matrix_sync(fah[mi], Ah + r, PMK);
            wmma::load_matrix_sync(fal[mi], Al + r, PMK);
        }
#pragma unroll
        for (int ni = 0; ni < 2; ++ni) {
            int r = (wn * 32 + ni * 16) * PMK + ks * 16;
            wmma::load_matrix_sync(fbh[ni], Bh + r, PMK);
            wmma::load_matrix_sync(fbl[ni], Bl + r, PMK);
        }
        TERM_MAJOR(acc, fah, fal, fbh, fbl);
    }
}

// MODE 1 (a_tilde = PA.b): A row-major mk, B row-major kn
__device__ __forceinline__ void compute_A(const char* st, FragC acc[2][2], int wm, int wn) {
    const __nv_bfloat16* Ah = (const __nv_bfloat16*)(st);
    const __nv_bfloat16* Al = (const __nv_bfloat16*)(st + 10240);
    const __nv_bfloat16* Bh = (const __nv_bfloat16*)(st + 20480);
    const __nv_bfloat16* Bl = (const __nv_bfloat16*)(st + 29184);
#pragma unroll
    for (int ks = 0; ks < 2; ++ks) {
        wmma::fragment<wmma::matrix_a, 16, 16, 16, __nv_bfloat16, wmma::row_major> fah[2], fal[2];
        wmma::fragment<wmma::matrix_b, 16, 16, 16, __nv_bfloat16, wmma::row_major> fbh[2], fbl[2];
#pragma unroll
        for (int mi = 0; mi < 2; ++mi) {
            int r = (wm * 32 + mi * 16) * PMK + ks * 16;
            wmma::load_matrix_sync(fah[mi], Ah + r, PMK);
            wmma::load_matrix_sync(fal[mi], Al + r, PMK);
        }
#pragma unroll
        for (int ni = 0; ni < 2; ++ni) {
            int r = ks * 16 * PKN + wn * 32 + ni * 16;
            wmma::load_matrix_sync(fbh[ni], Bh + r, PKN);
            wmma::load_matrix_sync(fbl[ni], Bl + r, PKN);
        }
        TERM_MAJOR(acc, fah, fal, fbh, fbl);
    }
}

// MODE 2 (b_tilde = PB^T.a): A col-major (tile [k][m] = PB natural rows), B row-major kn
__device__ __forceinline__ void compute_B(const char* st, FragC acc[2][2], int wm, int wn) {
    const __nv_bfloat16* Ah = (const __nv_bfloat16*)(st);
    const __nv_bfloat16* Al = (const __nv_bfloat16*)(st + 8704);
    const __nv_bfloat16* Bh = (const __nv_bfloat16*)(st + 17408);
    const __nv_bfloat16* Bl = (const __nv_bfloat16*)(st + 26112);
#pragma unroll
    for (int ks = 0; ks < 2; ++ks) {
        wmma::fragment<wmma::matrix_a, 16, 16, 16, __nv_bfloat16, wmma::col_major> fah[2], fal[2];
        wmma::fragment<wmma::matrix_b, 16, 16, 16, __nv_bfloat16, wmma::row_major> fbh[2], fbl[2];
#pragma unroll
        for (int mi = 0; mi < 2; ++mi) {
            int r = ks * 16 * PKN + wm * 32 + mi * 16;
            wmma::load_matrix_sync(fah[mi], Ah + r, PKN);
            wmma::load_matrix_sync(fal[mi], Al + r, PKN);
        }
#pragma unroll
        for (int ni = 0; ni < 2; ++ni) {
            int r = ks * 16 * PKN + wn * 32 + ni * 16;
            wmma::load_matrix_sync(fbh[ni], Bh + r, PKN);
            wmma::load_matrix_sync(fbl[ni], Bl + r, PKN);
        }
        TERM_MAJOR(acc, fah, fal, fbh, fbl);
    }
}

// ---------------------------------------------------------------------------
// GEMM body. MODE: 0=E, 1=a_tilde+m_a, 2=b_tilde+m_b
// Block tile 128x128, 512 threads, 4-stage cp.async bf16 pipeline.
// ---------------------------------------------------------------------------
template <int MODE>
__device__ __forceinline__ void gemm_body(const float* __restrict__ a,
                                          const float* __restrict__ bm,
                                          float* __restrict__ out, int bb) {
    constexpr int STAGE = (MODE == 0) ? 40960 : (MODE == 1) ? 37888 : 34816;
    extern __shared__ char sm[];
    uint32_t su = (uint32_t)__cvta_generic_to_shared(sm);

    int t = threadIdx.x, wid = t >> 5;
    int wm = wid & 3, wn = wid >> 2;
    int m0 = blockIdx.y * 128, n0 = blockIdx.x * 128;
    const size_t SS = (size_t)S * S;
    const size_t bo = (size_t)bb * SS;

    const __nv_bfloat16 *Ah, *Al, *Bh, *Bl;
    if (MODE == 0) { Ah = g_a_hi + bo + (size_t)m0 * S; Al = g_a_lo + bo + (size_t)m0 * S;
                     Bh = g_b_hi + bo + (size_t)n0 * S; Bl = g_b_lo + bo + (size_t)n0 * S; }
    if (MODE == 1) { Ah = g_pa_hi + bo + (size_t)m0 * S; Al = g_pa_lo + bo + (size_t)m0 * S;
                     Bh = g_b_hi + bo + n0;              Bl = g_b_lo + bo + n0; }
    if (MODE == 2) { Ah = g_pb_hi + bo + m0;             Al = g_pb_lo + bo + m0;
                     Bh = g_a_hi + bo + n0;              Bl = g_a_lo + bo + n0; }

#define CPSTAGE(c) do {                                                          \
        uint32_t stu_ = su + ((c) & 3) * STAGE;                                  \
        if (MODE == 2) { cp_kn(Ah + (size_t)(c) * 32 * S, stu_, t);              \
                         cp_kn(Al + (size_t)(c) * 32 * S, stu_ + 8704, t); }     \
        else           { cp_mk(Ah + (c) * 32, stu_, t);                          \
                         cp_mk(Al + (c) * 32, stu_ + 10240, t); }                \
        if (MODE == 0) { cp_mk(Bh + (c) * 32, stu_ + 20480, t);                  \
                         cp_mk(Bl + (c) * 32, stu_ + 30720, t); }                \
        else if (MODE == 1) { cp_kn(Bh + (size_t)(c) * 32 * S, stu_ + 20480, t); \
                              cp_kn(Bl + (size_t)(c) * 32 * S, stu_ + 29184, t);}\
        else           { cp_kn(Bh + (size_t)(c) * 32 * S, stu_ + 17408, t);      \
                         cp_kn(Bl + (size_t)(c) * 32 * S, stu_ + 26112, t); }    \
        CP_COMMIT(); } while (0)

    FragC acc[2][2];
#pragma unroll
    for (int mi = 0; mi < 2; ++mi)
#pragma unroll
        for (int ni = 0; ni < 2; ++ni) wmma::fill_fragment(acc[mi][ni], 0.0f);

    CPSTAGE(0); CPSTAGE(1); CPSTAGE(2);

#pragma unroll 1
    for (int c = 0; c < NC; ++c) {
        CP_WAIT(2);
        __syncthreads();
        if (c + 3 < NC) CPSTAGE(c + 3); else CP_COMMIT();
        const char* stage = sm + (c & 3) * STAGE;
        if (MODE == 0)      compute_E(stage, acc, wm, wn);
        else if (MODE == 1) compute_A(stage, acc, wm, wn);
        else                compute_B(stage, acc, wm, wn);
    }
    __syncthreads();

    if (MODE == 0) {
        float* Eb = g_E + bo + (size_t)m0 * S + n0;
#pragma unroll
        for (int mi = 0; mi < 2; ++mi)
#pragma unroll
            for (int ni = 0; ni < 2; ++ni)
                wmma::store_matrix_sync(Eb + (size_t)(wm * 32 + mi * 16) * S + wn * 32 + ni * 16,
                                        acc[mi][ni], S, wmma::mem_row_major);
        return;
    }

    // fused 4-way concat epilogue through smem staging
    float* fs = (float*)sm;
#pragma unroll
    for (int mi = 0; mi < 2; ++mi)
#pragma unroll
        for (int ni = 0; ni < 2; ++ni)
            wmma::store_matrix_sync(fs + (size_t)(wm * 32 + mi * 16) * PFS + wn * 32 + ni * 16,
                                    acc[mi][ni], PFS, wmma::mem_row_major);
    __syncthreads();

    const float* base = (MODE == 1) ? (a + ((size_t)bb * S + m0) * S + n0)
                                    : (bm + ((size_t)bb * S + m0) * S + n0);
    size_t obase = ((size_t)bb * S + m0) * 2048 + n0;
    if (MODE == 2) obase += (size_t)NB * S * 2048;
    float* ob = out + obase;
#pragma unroll
    for (int p = 0; p < 8; ++p) {
        int idx = t + p * NT;
        int r = idx >> 5, d4 = idx & 31;
        float4 xv = *(const float4*)(base + (size_t)r * S + 4 * d4);
        float4 tv = *(const float4*)(fs + (size_t)r * PFS + 4 * d4);
        float* o = ob + (size_t)r * 2048 + 4 * d4;
        *(float4*)(o)        = xv;
        *(float4*)(o + 512)  = tv;
        *(float4*)(o + 1024) = make_float4(xv.x - tv.x, xv.y - tv.y, xv.z - tv.z, xv.w - tv.w);
        *(float4*)(o + 1536) = make_float4(xv.x * tv.x, xv.y * tv.y, xv.z * tv.z, xv.w * tv.w);
    }
#undef CPSTAGE
}

// gemm0: E = a.b^T
__global__ __launch_bounds__(NT)
void k_gemm0(const float* __restrict__ a, const float* __restrict__ bm,
             float* __restrict__ out) {
    gemm_body<0>(a, bm, out, blockIdx.z);
}

// merged output GEMMs: z<NB -> mode 1 (m_a), z>=NB -> mode 2 (m_b).
// One 1024-block launch: halves wave-quantization tail vs two 512-block launches.
__global__ __launch_bounds__(NT)
void k_gemm12(const float* __restrict__ a, const float* __restrict__ bm,
              float* __restrict__ out) {
    if (blockIdx.z < NB) gemm_body<1>(a, bm, out, blockIdx.z);
    else                 gemm_body<2>(a, bm, out, blockIdx.z - NB);
}

// ---------------------------------------------------------------------------

extern "C" void kernel_launch(void* const* d_in, const int* in_sizes, int n_in,
                              void* d_out, int out_size) {
    const float* a  = (const float*)d_in[0];
    const float* bm = (const float*)d_in[1];
    float* out = (float*)d_out;
    (void)in_sizes; (void)n_in; (void)out_size;

    const int SM0  = NSTG * 40960;   // 163840
    const int SM12 = NSTG * 37888;   // 151552 (max of mode1/mode2 stage sizes)

    static int configured = 0;
    if (!configured) {
        cudaFuncSetAttribute(k_gemm0,  cudaFuncAttributeMaxDynamicSharedMemorySize, SM0);
        cudaFuncSetAttribute(k_gemm12, cudaFuncAttributeMaxDynamicSharedMemorySize, SM12);
        configured = 1;
    }

    k_split<<<dim3(8192, 2), 256>>>(a, bm);
    k_gemm0<<<dim3(4, 4, NB), NT, SM0>>>(a, bm, out);
    k_row_stats<<<NB * S / 8, 256>>>();
    k_col_stats<<<dim3(S / 64, NB), 256>>>();
    k_pmat<<<dim3(S / 8, NB), 256>>>();
    k_gemm12<<<dim3(4, 4, 2 * NB), NT, SM12>>>(a, bm, out);
}

// round 10
// speedup vs baseline: 2.4436x; 1.2086x over previous
#include <cuda_runtime.h>
#include <cuda_bf16.h>
#include <cstdint>

#define NB 32
#define S  512
#define NC 16            // K chunks of 32 (K=512)
#define NT 512           // threads per GEMM block
#define NSTG 4
#define STAGE 40960      // unified stage size (bytes)
#define PGRID 148        // persistent grid
#define PKN_B 272        // kn tile pitch bytes (32 rows)
#define PMK_B 80         // mk tile pitch bytes (128 rows)
#define PFS 136          // f32 epilogue staging pitch (elements)

// ---------------------------------------------------------------------------
// Device-global scratch (allocation-free per harness rules)
// ---------------------------------------------------------------------------
__device__ __align__(16) float g_E[(size_t)NB * S * S];
__device__ float g_rmax[NB * S], g_rinv[NB * S];
__device__ float g_cmax[NB * S], g_cinv[NB * S];
__device__ unsigned int g_ctr0, g_ctr12;

#define BFARR(name) __device__ __align__(16) __nv_bfloat16 name[(size_t)NB * S * S]
BFARR(g_a_hi);  BFARR(g_a_lo);
BFARR(g_b_hi);  BFARR(g_b_lo);
BFARR(g_pa_hi); BFARR(g_pa_lo);
BFARR(g_pb_hi); BFARR(g_pb_lo);

// ---------------------------------------------------------------------------
// cp.async helpers
// ---------------------------------------------------------------------------
__device__ __forceinline__ void cp16(uint32_t dst, const void* src) {
    asm volatile("cp.async.cg.shared.global [%0], [%1], 16;" :: "r"(dst), "l"(src));
}
#define CP_COMMIT() asm volatile("cp.async.commit_group;" ::: "memory")
#define CP_WAIT(n)  asm volatile("cp.async.wait_group %0;" :: "n"(n) : "memory")

__device__ __forceinline__ void cp_mk(const __nv_bfloat16* __restrict__ src, uint32_t du, int t) {
    int row = t >> 2, c = t & 3;
    cp16(du + row * PMK_B + c * 16, src + (size_t)row * S + c * 8);
}
__device__ __forceinline__ void cp_kn(const __nv_bfloat16* __restrict__ src, uint32_t du, int t) {
    int row = t >> 4, c = t & 15;
    cp16(du + row * PKN_B + c * 16, src + (size_t)row * S + c * 8);
}

// ---------------------------------------------------------------------------
// split helpers
// ---------------------------------------------------------------------------
__device__ __forceinline__ void split2(float x, unsigned short& h, unsigned short& l) {
    __nv_bfloat16 hb = __float2bfloat16(x);
    __nv_bfloat16 lb = __float2bfloat16(x - __bfloat162float(hb));
    h = __bfloat16_as_ushort(hb); l = __bfloat16_as_ushort(lb);
}
__device__ __forceinline__ void split4(float4 v, ushort4& h4, ushort4& l4) {
    split2(v.x, h4.x, l4.x); split2(v.y, h4.y, l4.y);
    split2(v.z, h4.z, l4.z); split2(v.w, h4.w, l4.w);
}

// ---------------------------------------------------------------------------
// K0: elementwise split a,b -> hi/lo bf16; also resets task counters
// ---------------------------------------------------------------------------
__global__ __launch_bounds__(256)
void k_split(const float* __restrict__ a, const float* __restrict__ bm) {
    if (blockIdx.x == 0 && blockIdx.y == 0 && threadIdx.x == 0) {
        g_ctr0 = 0; g_ctr12 = 0;
    }
    const float* src = blockIdx.y ? bm : a;
    __nv_bfloat16* hi = blockIdx.y ? g_b_hi : g_a_hi;
    __nv_bfloat16* lo = blockIdx.y ? g_b_lo : g_a_lo;
    size_t i4 = (size_t)blockIdx.x * 256 + threadIdx.x;
    float4 v = ((const float4*)src)[i4];
    ushort4 h4, l4; split4(v, h4, l4);
    ((ushort4*)hi)[i4] = h4;
    ((ushort4*)lo)[i4] = l4;
}

// ---------------------------------------------------------------------------
// Row / column softmax stats
// ---------------------------------------------------------------------------
__global__ __launch_bounds__(256)
void k_row_stats() {
    int wid = threadIdx.x >> 5, lane = threadIdx.x & 31;
    size_t row = (size_t)blockIdx.x * 8 + wid;
    const float* e = g_E + row * S;
    float4 v[4];
#pragma unroll
    for (int p = 0; p < 4; ++p) v[p] = *(const float4*)(e + lane * 4 + p * 128);
    float m = -3.402823466e38f;
#pragma unroll
    for (int p = 0; p < 4; ++p)
        m = fmaxf(m, fmaxf(fmaxf(v[p].x, v[p].y), fmaxf(v[p].z, v[p].w)));
#pragma unroll
    for (int o = 16; o; o >>= 1) m = fmaxf(m, __shfl_xor_sync(0xffffffffu, m, o));
    float s = 0.0f;
#pragma unroll
    for (int p = 0; p < 4; ++p)
        s += __expf(v[p].x - m) + __expf(v[p].y - m) + __expf(v[p].z - m) + __expf(v[p].w - m);
#pragma unroll
    for (int o = 16; o; o >>= 1) s += __shfl_xor_sync(0xffffffffu, s, o);
    if (lane == 0) { g_rmax[row] = m; g_rinv[row] = 1.0f / s; }
}

__global__ __launch_bounds__(256)
void k_col_stats() {
    int b  = blockIdx.y;
    int j0 = blockIdx.x * 64;
    int c  = threadIdx.x & 63;
    int r  = threadIdx.x >> 6;
    int j  = j0 + c;
    const float* e = g_E + (size_t)b * S * S + j;
    float m = -3.402823466e38f, s = 0.0f;
    for (int i = r * 128; i < (r + 1) * 128; ++i) {
        float v  = e[(size_t)i * S];
        float nm = fmaxf(m, v);
        s = s * __expf(m - nm) + __expf(v - nm);
        m = nm;
    }
    __shared__ float sm2[4][64], ss2[4][64];
    sm2[r][c] = m; ss2[r][c] = s;
    __syncthreads();
    if (r == 0) {
        float M = m, Sv = s;
#pragma unroll
        for (int q = 1; q < 4; ++q) {
            float m2 = sm2[q][c], s2 = ss2[q][c];
            float nm = fmaxf(M, m2);
            Sv = Sv * __expf(M - nm) + s2 * __expf(m2 - nm);
            M = nm;
        }
        g_cmax[b * S + j] = M;
        g_cinv[b * S + j] = 1.0f / Sv;
    }
}

// ---------------------------------------------------------------------------
// K_pmat: one pass over E -> PA hi/lo (row softmax), PB hi/lo (col softmax)
// ---------------------------------------------------------------------------
__global__ __launch_bounds__(256)
void k_pmat() {
    __shared__ float cm[S], ci[S];
    int b = blockIdx.y, r0 = blockIdx.x * 8;
    int t = threadIdx.x;
    for (int idx = t; idx < S; idx += 256) {
        cm[idx] = g_cmax[b * S + idx];
        ci[idx] = g_cinv[b * S + idx];
    }
    __syncthreads();
    int row = r0 + (t >> 5);
    int jb  = (t & 31) * 16;
    size_t base = (size_t)b * S * S + (size_t)row * S + jb;
    float rm = g_rmax[b * S + row], rv = g_rinv[b * S + row];
#pragma unroll
    for (int q = 0; q < 4; ++q) {
        float4 v = *(const float4*)(g_E + base + q * 4);
        int j = jb + q * 4;
        float4 pa = make_float4(__expf(v.x - rm) * rv, __expf(v.y - rm) * rv,
                                __expf(v.z - rm) * rv, __expf(v.w - rm) * rv);
        float4 pb = make_float4(__expf(v.x - cm[j]) * ci[j],
                                __expf(v.y - cm[j + 1]) * ci[j + 1],
                                __expf(v.z - cm[j + 2]) * ci[j + 2],
                                __expf(v.w - cm[j + 3]) * ci[j + 3]);
        ushort4 h4, l4;
        split4(pa, h4, l4);
        *(ushort4*)(g_pa_hi + base + q * 4) = h4;
        *(ushort4*)(g_pa_lo + base + q * 4) = l4;
        split4(pb, h4, l4);
        *(ushort4*)(g_pb_hi + base + q * 4) = h4;
        *(ushort4*)(g_pb_lo + base + q * 4) = l4;
    }
}

// ---------------------------------------------------------------------------
// Raw PTX: ldmatrix + mma.sync
// ---------------------------------------------------------------------------
__device__ __forceinline__ void ldm4(uint32_t* r, uint32_t a) {
    asm volatile("ldmatrix.sync.aligned.m8n8.x4.shared.b16 {%0,%1,%2,%3}, [%4];"
                 : "=r"(r[0]), "=r"(r[1]), "=r"(r[2]), "=r"(r[3]) : "r"(a));
}
__device__ __forceinline__ void ldm4t(uint32_t* r, uint32_t a) {
    asm volatile("ldmatrix.sync.aligned.m8n8.x4.trans.shared.b16 {%0,%1,%2,%3}, [%4];"
                 : "=r"(r[0]), "=r"(r[1]), "=r"(r[2]), "=r"(r[3]) : "r"(a));
}
__device__ __forceinline__ void mma16816(float* c, const uint32_t* a, const uint32_t* b) {
    asm volatile("mma.sync.aligned.m16n8k16.row.col.f32.bf16.bf16.f32 "
                 "{%0,%1,%2,%3}, {%4,%5,%6,%7}, {%8,%9}, {%0,%1,%2,%3};"
                 : "+f"(c[0]), "+f"(c[1]), "+f"(c[2]), "+f"(c[3])
                 : "r"(a[0]), "r"(a[1]), "r"(a[2]), "r"(a[3]), "r"(b[0]), "r"(b[1]));
}

// ---------------------------------------------------------------------------
// compute one 32-k chunk: 16 warps, warp tile 32m x 32n, 3-term split bf16.
// acc[mi(2)][nf(4)][4].  Term-major: reuse distance 8.
// ---------------------------------------------------------------------------
template <int MODE>
__device__ __forceinline__ void compute_chunk(uint32_t sb, float acc[2][4][4],
                                              int wm, int wn, int lane) {
    const uint32_t A_hi = sb;
    const uint32_t A_lo = sb + ((MODE == 2) ? 8704 : 10240);
    const uint32_t B_hi = sb + 20480;
    const uint32_t B_lo = sb + ((MODE == 0) ? 30720 : 29184);
#pragma unroll
    for (int ks = 0; ks < 2; ++ks) {
        uint32_t ah[2][4], al[2][4], bh[4][2], bl[4][2];
#pragma unroll
        for (int mi = 0; mi < 2; ++mi) {
            uint32_t ao;
            if (MODE == 2)
                ao = (uint32_t)((ks * 16 + (lane & 7) + ((lane >> 4) << 3)) * PKN_B
                                + (wm * 32 + mi * 16 + (((lane >> 3) & 1) << 3)) * 2);
            else
                ao = (uint32_t)((wm * 32 + mi * 16 + (lane & 15)) * PMK_B
                                + ks * 32 + ((lane >> 4) << 4));
            if (MODE == 2) { ldm4t(ah[mi], A_hi + ao); ldm4t(al[mi], A_lo + ao); }
            else           { ldm4 (ah[mi], A_hi + ao); ldm4 (al[mi], A_lo + ao); }
        }
#pragma unroll
        for (int nb = 0; nb < 2; ++nb) {
            uint32_t bo, r4[4];
            if (MODE == 0)
                bo = (uint32_t)((wn * 32 + nb * 16 + (lane & 7) + ((lane >> 4) << 3)) * PMK_B
                                + ks * 32 + (((lane >> 3) & 1) << 4));
            else
                bo = (uint32_t)((ks * 16 + (lane & 15)) * PKN_B
                                + (wn * 32 + nb * 16 + ((lane >> 4) << 3)) * 2);
            if (MODE == 0) ldm4(r4, B_hi + bo); else ldm4t(r4, B_hi + bo);
            bh[nb * 2][0] = r4[0]; bh[nb * 2][1] = r4[1];
            bh[nb * 2 + 1][0] = r4[2]; bh[nb * 2 + 1][1] = r4[3];
            if (MODE == 0) ldm4(r4, B_lo + bo); else ldm4t(r4, B_lo + bo);
            bl[nb * 2][0] = r4[0]; bl[nb * 2][1] = r4[1];
            bl[nb * 2 + 1][0] = r4[2]; bl[nb * 2 + 1][1] = r4[3];
        }
#pragma unroll
        for (int mi = 0; mi < 2; ++mi)
#pragma unroll
            for (int nf = 0; nf < 4; ++nf) mma16816(acc[mi][nf], ah[mi], bh[nf]);
#pragma unroll
        for (int mi = 0; mi < 2; ++mi)
#pragma unroll
            for (int nf = 0; nf < 4; ++nf) mma16816(acc[mi][nf], ah[mi], bl[nf]);
#pragma unroll
        for (int mi = 0; mi < 2; ++mi)
#pragma unroll
            for (int nf = 0; nf < 4; ++nf) mma16816(acc[mi][nf], al[mi], bh[nf]);
    }
}

// ---------------------------------------------------------------------------
// One 128x128 tile task. MODE: 0=E, 1=a_tilde+m_a, 2=b_tilde+m_b
// ---------------------------------------------------------------------------
template <int MODE>
__device__ __forceinline__ void gemm_tile(const float* __restrict__ a,
                                          const float* __restrict__ bm,
                                          float* __restrict__ out,
                                          int bb, int m0, int n0) {
    extern __shared__ char sm[];
    uint32_t su = (uint32_t)__cvta_generic_to_shared(sm);
    int t = threadIdx.x, wid = t >> 5, lane = t & 31;
    int wm = wid & 3, wn = wid >> 2;
    const size_t bo = (size_t)bb * S * S;

    const __nv_bfloat16 *Ah, *Al, *Bh, *Bl;
    if (MODE == 0) { Ah = g_a_hi + bo + (size_t)m0 * S; Al = g_a_lo + bo + (size_t)m0 * S;
                     Bh = g_b_hi + bo + (size_t)n0 * S; Bl = g_b_lo + bo + (size_t)n0 * S; }
    if (MODE == 1) { Ah = g_pa_hi + bo + (size_t)m0 * S; Al = g_pa_lo + bo + (size_t)m0 * S;
                     Bh = g_b_hi + bo + n0;              Bl = g_b_lo + bo + n0; }
    if (MODE == 2) { Ah = g_pb_hi + bo + m0;             Al = g_pb_lo + bo + m0;
                     Bh = g_a_hi + bo + n0;              Bl = g_a_lo + bo + n0; }

#define CPSTAGE(c) do {                                                          \
        uint32_t stu_ = su + ((c) & 3) * STAGE;                                  \
        if (MODE == 2) { cp_kn(Ah + (size_t)(c) * 32 * S, stu_, t);              \
                         cp_kn(Al + (size_t)(c) * 32 * S, stu_ + 8704, t); }     \
        else           { cp_mk(Ah + (c) * 32, stu_, t);                          \
                         cp_mk(Al + (c) * 32, stu_ + 10240, t); }                \
        if (MODE == 0) { cp_mk(Bh + (c) * 32, stu_ + 20480, t);                  \
                         cp_mk(Bl + (c) * 32, stu_ + 30720, t); }                \
        else           { cp_kn(Bh + (size_t)(c) * 32 * S, stu_ + 20480, t);      \
                         cp_kn(Bl + (size_t)(c) * 32 * S, stu_ + 29184, t); }    \
        CP_COMMIT(); } while (0)

    float acc[2][4][4] = {};

    CPSTAGE(0); CPSTAGE(1); CPSTAGE(2);

#pragma unroll 1
    for (int c = 0; c < NC; ++c) {
        CP_WAIT(2);
        __syncthreads();
        if (c + 3 < NC) CPSTAGE(c + 3); else CP_COMMIT();
        compute_chunk<MODE>(su + (c & 3) * STAGE, acc, wm, wn, lane);
    }
    __syncthreads();

    int r  = lane >> 2;
    int cg = (lane & 3) * 2;

    if (MODE == 0) {
        float* Eb = g_E + bo;
#pragma unroll
        for (int mi = 0; mi < 2; ++mi)
#pragma unroll
            for (int nf = 0; nf < 4; ++nf) {
                int m = m0 + wm * 32 + mi * 16 + r;
                int n = n0 + wn * 32 + nf * 8 + cg;
                *(float2*)(Eb + (size_t)m * S + n)       = make_float2(acc[mi][nf][0], acc[mi][nf][1]);
                *(float2*)(Eb + (size_t)(m + 8) * S + n) = make_float2(acc[mi][nf][2], acc[mi][nf][3]);
            }
        return;
    }

    // stage result in smem, fused 4-way concat epilogue
    float* fs = (float*)sm;
#pragma unroll
    for (int mi = 0; mi < 2; ++mi)
#pragma unroll
        for (int nf = 0; nf < 4; ++nf) {
            int m = wm * 32 + mi * 16 + r;
            int n = wn * 32 + nf * 8 + cg;
            *(float2*)(fs + (size_t)m * PFS + n)       = make_float2(acc[mi][nf][0], acc[mi][nf][1]);
            *(float2*)(fs + (size_t)(m + 8) * PFS + n) = make_float2(acc[mi][nf][2], acc[mi][nf][3]);
        }
    __syncthreads();

    const float* base = (MODE == 1) ? (a + ((size_t)bb * S + m0) * S + n0)
                                    : (bm + ((size_t)bb * S + m0) * S + n0);
    size_t obase = ((size_t)bb * S + m0) * 2048 + n0;
    if (MODE == 2) obase += (size_t)NB * S * 2048;
    float* ob = out + obase;
#pragma unroll
    for (int p = 0; p < 8; ++p) {
        int idx = t + p * NT;
        int rr = idx >> 5, d4 = idx & 31;
        float4 xv = *(const float4*)(base + (size_t)rr * S + 4 * d4);
        float4 tv = *(const float4*)(fs + (size_t)rr * PFS + 4 * d4);
        float* o = ob + (size_t)rr * 2048 + 4 * d4;
        *(float4*)(o)        = xv;
        *(float4*)(o + 512)  = tv;
        *(float4*)(o + 1024) = make_float4(xv.x - tv.x, xv.y - tv.y, xv.z - tv.z, xv.w - tv.w);
        *(float4*)(o + 1536) = make_float4(xv.x * tv.x, xv.y * tv.y, xv.z * tv.z, xv.w * tv.w);
    }
#undef CPSTAGE
}

// ---------------------------------------------------------------------------
// Persistent GEMM kernels with dynamic tile scheduling
// ---------------------------------------------------------------------------
__global__ __launch_bounds__(NT)
void k_gemm0p(const float* __restrict__ a, const float* __restrict__ bm,
              float* __restrict__ out) {
    __shared__ unsigned task_s;
    for (;;) {
        if (threadIdx.x == 0) task_s = atomicAdd(&g_ctr0, 1u);
        __syncthreads();
        unsigned task = task_s;
        if (task >= 512u) break;
        int bb = task >> 4, m0 = ((task >> 2) & 3) * 128, n0 = (task & 3) * 128;
        gemm_tile<0>(a, bm, out, bb, m0, n0);
        __syncthreads();
    }
}

__global__ __launch_bounds__(NT)
void k_gemm12p(const float* __restrict__ a, const float* __restrict__ bm,
               float* __restrict__ out) {
    __shared__ unsigned task_s;
    for (;;) {
        if (threadIdx.x == 0) task_s = atomicAdd(&g_ctr12, 1u);
        __syncthreads();
        unsigned task = task_s;
        if (task >= 1024u) break;
        unsigned sub = task & 511u;
        int bb = sub >> 4, m0 = ((sub >> 2) & 3) * 128, n0 = (sub & 3) * 128;
        if (task < 512u) gemm_tile<1>(a, bm, out, bb, m0, n0);
        else             gemm_tile<2>(a, bm, out, bb, m0, n0);
        __syncthreads();
    }
}

// ---------------------------------------------------------------------------

extern "C" void kernel_launch(void* const* d_in, const int* in_sizes, int n_in,
                              void* d_out, int out_size) {
    const float* a  = (const float*)d_in[0];
    const float* bm = (const float*)d_in[1];
    float* out = (float*)d_out;
    (void)in_sizes; (void)n_in; (void)out_size;

    const int SMEM = NSTG * STAGE;   // 163840

    static int configured = 0;
    if (!configured) {
        cudaFuncSetAttribute(k_gemm0p,  cudaFuncAttributeMaxDynamicSharedMemorySize, SMEM);
        cudaFuncSetAttribute(k_gemm12p, cudaFuncAttributeMaxDynamicSharedMemorySize, SMEM);
        configured = 1;
    }

    k_split<<<dim3(8192, 2), 256>>>(a, bm);
    k_gemm0p<<<PGRID, NT, SMEM>>>(a, bm, out);
    k_row_stats<<<NB * S / 8, 256>>>();
    k_col_stats<<<dim3(S / 64, NB), 256>>>();
    k_pmat<<<dim3(S / 8, NB), 256>>>();
    k_gemm12p<<<PGRID, NT, SMEM>>>(a, bm, out);
}

// round 11
// speedup vs baseline: 3.2459x; 1.3283x over previous
#include <cuda_runtime.h>
#include <cuda_fp16.h>
#include <cstdint>

#define NB 32
#define S  512
#define NC 16            // K chunks of 32 (K=512)
#define NT 512           // threads per GEMM block
#define NSTG 4
#define STAGE0  40960    // mode0 stage bytes (4 tiles x 10240)
#define STAGE12 18944    // modes 1/2 stage bytes (A + B single tiles)
#define PGRID 148
#define PKN_B 272        // kn tile pitch bytes (32 rows x 256B data)
#define PMK_B 80         // mk tile pitch bytes (128 rows x 64B data)
#define PFS 136          // f32 epilogue staging pitch (elements)

// ---------------------------------------------------------------------------
// Device-global scratch
// ---------------------------------------------------------------------------
__device__ __align__(16) float g_E[(size_t)NB * S * S];
__device__ float g_rmax[NB * S], g_rinv[NB * S];
__device__ float g_cmax[NB * S], g_cinv[NB * S];
__device__ unsigned int g_ctr0, g_ctr12;

#define HARR(name) __device__ __align__(16) __half name[(size_t)NB * S * S]
HARR(g_a_hi); HARR(g_a_lo);   // a split fp16 (E-gemm); a_hi also = gemm2 B operand
HARR(g_b_hi); HARR(g_b_lo);   // b split fp16 (E-gemm); b_hi also = gemm1 B operand
HARR(g_pa);                   // row-softmax(E), single fp16
HARR(g_pb);                   // col-softmax(E), single fp16

// ---------------------------------------------------------------------------
// cp.async helpers
// ---------------------------------------------------------------------------
__device__ __forceinline__ void cp16(uint32_t dst, const void* src) {
    asm volatile("cp.async.cg.shared.global [%0], [%1], 16;" :: "r"(dst), "l"(src));
}
#define CP_COMMIT() asm volatile("cp.async.commit_group;" ::: "memory")
#define CP_WAIT(n)  asm volatile("cp.async.wait_group %0;" :: "n"(n) : "memory")

__device__ __forceinline__ void cp_mk(const __half* __restrict__ src, uint32_t du, int t) {
    int row = t >> 2, c = t & 3;
    cp16(du + row * PMK_B + c * 16, src + (size_t)row * S + c * 8);
}
__device__ __forceinline__ void cp_kn(const __half* __restrict__ src, uint32_t du, int t) {
    int row = t >> 4, c = t & 15;
    cp16(du + row * PKN_B + c * 16, src + (size_t)row * S + c * 8);
}

// ---------------------------------------------------------------------------
// fp16 split helpers
// ---------------------------------------------------------------------------
__device__ __forceinline__ void split2(float x, unsigned short& h, unsigned short& l) {
    __half hb = __float2half_rn(x);
    __half lb = __float2half_rn(x - __half2float(hb));
    h = __half_as_ushort(hb); l = __half_as_ushort(lb);
}
__device__ __forceinline__ void split4(float4 v, ushort4& h4, ushort4& l4) {
    split2(v.x, h4.x, l4.x); split2(v.y, h4.y, l4.y);
    split2(v.z, h4.z, l4.z); split2(v.w, h4.w, l4.w);
}
__device__ __forceinline__ ushort4 h4_of(float4 v) {
    return make_ushort4(__half_as_ushort(__float2half_rn(v.x)),
                        __half_as_ushort(__float2half_rn(v.y)),
                        __half_as_ushort(__float2half_rn(v.z)),
                        __half_as_ushort(__float2half_rn(v.w)));
}

// ---------------------------------------------------------------------------
// K0: split a,b -> fp16 hi/lo; reset task counters
// ---------------------------------------------------------------------------
__global__ __launch_bounds__(256)
void k_split(const float* __restrict__ a, const float* __restrict__ bm) {
    if (blockIdx.x == 0 && blockIdx.y == 0 && threadIdx.x == 0) {
        g_ctr0 = 0; g_ctr12 = 0;
    }
    const float* src = blockIdx.y ? bm : a;
    __half* hi = blockIdx.y ? g_b_hi : g_a_hi;
    __half* lo = blockIdx.y ? g_b_lo : g_a_lo;
    size_t i4 = (size_t)blockIdx.x * 256 + threadIdx.x;
    float4 v = ((const float4*)src)[i4];
    ushort4 h4, l4; split4(v, h4, l4);
    ((ushort4*)hi)[i4] = h4;
    ((ushort4*)lo)[i4] = l4;
}

// ---------------------------------------------------------------------------
// Row / column softmax stats
// ---------------------------------------------------------------------------
__global__ __launch_bounds__(256)
void k_row_stats() {
    int wid = threadIdx.x >> 5, lane = threadIdx.x & 31;
    size_t row = (size_t)blockIdx.x * 8 + wid;
    const float* e = g_E + row * S;
    float4 v[4];
#pragma unroll
    for (int p = 0; p < 4; ++p) v[p] = *(const float4*)(e + lane * 4 + p * 128);
    float m = -3.402823466e38f;
#pragma unroll
    for (int p = 0; p < 4; ++p)
        m = fmaxf(m, fmaxf(fmaxf(v[p].x, v[p].y), fmaxf(v[p].z, v[p].w)));
#pragma unroll
    for (int o = 16; o; o >>= 1) m = fmaxf(m, __shfl_xor_sync(0xffffffffu, m, o));
    float s = 0.0f;
#pragma unroll
    for (int p = 0; p < 4; ++p)
        s += __expf(v[p].x - m) + __expf(v[p].y - m) + __expf(v[p].z - m) + __expf(v[p].w - m);
#pragma unroll
    for (int o = 16; o; o >>= 1) s += __shfl_xor_sync(0xffffffffu, s, o);
    if (lane == 0) { g_rmax[row] = m; g_rinv[row] = 1.0f / s; }
}

__global__ __launch_bounds__(512)
void k_col_stats() {
    int b  = blockIdx.y;
    int j0 = blockIdx.x * 64;
    int c  = threadIdx.x & 63;
    int r  = threadIdx.x >> 6;      // 0..7
    int j  = j0 + c;
    const float* e = g_E + (size_t)b * S * S + j;
    float m = -3.402823466e38f, s = 0.0f;
    for (int i = r * 64; i < (r + 1) * 64; ++i) {
        float v  = e[(size_t)i * S];
        float nm = fmaxf(m, v);
        s = s * __expf(m - nm) + __expf(v - nm);
        m = nm;
    }
    __shared__ float sm2[8][64], ss2[8][64];
    sm2[r][c] = m; ss2[r][c] = s;
    __syncthreads();
    if (r == 0) {
        float M = m, Sv = s;
#pragma unroll
        for (int q = 1; q < 8; ++q) {
            float m2 = sm2[q][c], s2 = ss2[q][c];
            float nm = fmaxf(M, m2);
            Sv = Sv * __expf(M - nm) + s2 * __expf(m2 - nm);
            M = nm;
        }
        g_cmax[b * S + j] = M;
        g_cinv[b * S + j] = 1.0f / Sv;
    }
}

// ---------------------------------------------------------------------------
// K_pmat: one pass over E -> PA (row softmax, fp16), PB (col softmax, fp16)
// ---------------------------------------------------------------------------
__global__ __launch_bounds__(256)
void k_pmat() {
    __shared__ float cm[S], ci[S];
    int b = blockIdx.y, r0 = blockIdx.x * 8;
    int t = threadIdx.x;
    for (int idx = t; idx < S; idx += 256) {
        cm[idx] = g_cmax[b * S + idx];
        ci[idx] = g_cinv[b * S + idx];
    }
    __syncthreads();
    int row = r0 + (t >> 5);
    int jb  = (t & 31) * 16;
    size_t base = (size_t)b * S * S + (size_t)row * S + jb;
    float rm = g_rmax[b * S + row], rv = g_rinv[b * S + row];
#pragma unroll
    for (int q = 0; q < 4; ++q) {
        float4 v = *(const float4*)(g_E + base + q * 4);
        int j = jb + q * 4;
        float4 pa = make_float4(__expf(v.x - rm) * rv, __expf(v.y - rm) * rv,
                                __expf(v.z - rm) * rv, __expf(v.w - rm) * rv);
        float4 pb = make_float4(__expf(v.x - cm[j]) * ci[j],
                                __expf(v.y - cm[j + 1]) * ci[j + 1],
                                __expf(v.z - cm[j + 2]) * ci[j + 2],
                                __expf(v.w - cm[j + 3]) * ci[j + 3]);
        *(ushort4*)(g_pa + base + q * 4) = h4_of(pa);
        *(ushort4*)(g_pb + base + q * 4) = h4_of(pb);
    }
}

// ---------------------------------------------------------------------------
// Raw PTX: ldmatrix + mma.sync (fp16 in, fp32 accum)
// ---------------------------------------------------------------------------
__device__ __forceinline__ void ldm4(uint32_t* r, uint32_t a) {
    asm volatile("ldmatrix.sync.aligned.m8n8.x4.shared.b16 {%0,%1,%2,%3}, [%4];"
                 : "=r"(r[0]), "=r"(r[1]), "=r"(r[2]), "=r"(r[3]) : "r"(a));
}
__device__ __forceinline__ void ldm4t(uint32_t* r, uint32_t a) {
    asm volatile("ldmatrix.sync.aligned.m8n8.x4.trans.shared.b16 {%0,%1,%2,%3}, [%4];"
                 : "=r"(r[0]), "=r"(r[1]), "=r"(r[2]), "=r"(r[3]) : "r"(a));
}
__device__ __forceinline__ void mma16816(float* c, const uint32_t* a, const uint32_t* b) {
    asm volatile("mma.sync.aligned.m16n8k16.row.col.f32.f16.f16.f32 "
                 "{%0,%1,%2,%3}, {%4,%5,%6,%7}, {%8,%9}, {%0,%1,%2,%3};"
                 : "+f"(c[0]), "+f"(c[1]), "+f"(c[2]), "+f"(c[3])
                 : "r"(a[0]), "r"(a[1]), "r"(a[2]), "r"(a[3]), "r"(b[0]), "r"(b[1]));
}

// ---------------------------------------------------------------------------
// compute one 32-k chunk. MODE 0: 3-term split. MODES 1/2: single term.
// 16 warps, warp tile 32m x 32n. acc[mi(2)][nf(4)][4].
// ---------------------------------------------------------------------------
template <int MODE>
__device__ __forceinline__ void compute_chunk(uint32_t sb, float acc[2][4][4],
                                              int wm, int wn, int lane) {
    if (MODE == 0) {
        const uint32_t A_hi = sb, A_lo = sb + 10240;
        const uint32_t B_hi = sb + 20480, B_lo = sb + 30720;
#pragma unroll
        for (int ks = 0; ks < 2; ++ks) {
            uint32_t ah[2][4], al[2][4], bh[4][2], bl[4][2];
#pragma unroll
            for (int mi = 0; mi < 2; ++mi) {
                uint32_t ao = (uint32_t)((wm * 32 + mi * 16 + (lane & 15)) * PMK_B
                                         + ks * 32 + ((lane >> 4) << 4));
                ldm4(ah[mi], A_hi + ao); ldm4(al[mi], A_lo + ao);
            }
#pragma unroll
            for (int nb = 0; nb < 2; ++nb) {
                uint32_t bo = (uint32_t)((wn * 32 + nb * 16 + (lane & 7) + ((lane >> 4) << 3)) * PMK_B
                                         + ks * 32 + (((lane >> 3) & 1) << 4));
                uint32_t r4[4];
                ldm4(r4, B_hi + bo);
                bh[nb * 2][0] = r4[0]; bh[nb * 2][1] = r4[1];
                bh[nb * 2 + 1][0] = r4[2]; bh[nb * 2 + 1][1] = r4[3];
                ldm4(r4, B_lo + bo);
                bl[nb * 2][0] = r4[0]; bl[nb * 2][1] = r4[1];
                bl[nb * 2 + 1][0] = r4[2]; bl[nb * 2 + 1][1] = r4[3];
            }
#pragma unroll
            for (int mi = 0; mi < 2; ++mi)
#pragma unroll
                for (int nf = 0; nf < 4; ++nf) mma16816(acc[mi][nf], ah[mi], bh[nf]);
#pragma unroll
            for (int mi = 0; mi < 2; ++mi)
#pragma unroll
                for (int nf = 0; nf < 4; ++nf) mma16816(acc[mi][nf], ah[mi], bl[nf]);
#pragma unroll
            for (int mi = 0; mi < 2; ++mi)
#pragma unroll
                for (int nf = 0; nf < 4; ++nf) mma16816(acc[mi][nf], al[mi], bh[nf]);
        }
    } else {
        const uint32_t A0 = sb, B0 = sb + 10240;
#pragma unroll
        for (int ks = 0; ks < 2; ++ks) {
            uint32_t ah[2][4], bh[4][2];
#pragma unroll
            for (int mi = 0; mi < 2; ++mi) {
                if (MODE == 2) {
                    uint32_t ao = (uint32_t)((ks * 16 + (lane & 7) + ((lane >> 4) << 3)) * PKN_B
                                             + (wm * 32 + mi * 16 + (((lane >> 3) & 1) << 3)) * 2);
                    ldm4t(ah[mi], A0 + ao);
                } else {
                    uint32_t ao = (uint32_t)((wm * 32 + mi * 16 + (lane & 15)) * PMK_B
                                             + ks * 32 + ((lane >> 4) << 4));
                    ldm4(ah[mi], A0 + ao);
                }
            }
#pragma unroll
            for (int nb = 0; nb < 2; ++nb) {
                uint32_t bo = (uint32_t)((ks * 16 + (lane & 15)) * PKN_B
                                         + (wn * 32 + nb * 16 + ((lane >> 4) << 3)) * 2);
                uint32_t r4[4];
                ldm4t(r4, B0 + bo);
                bh[nb * 2][0] = r4[0]; bh[nb * 2][1] = r4[1];
                bh[nb * 2 + 1][0] = r4[2]; bh[nb * 2 + 1][1] = r4[3];
            }
#pragma unroll
            for (int mi = 0; mi < 2; ++mi)
#pragma unroll
                for (int nf = 0; nf < 4; ++nf) mma16816(acc[mi][nf], ah[mi], bh[nf]);
        }
    }
}

// ---------------------------------------------------------------------------
// One 128x128 tile task. MODE: 0=E, 1=a_tilde+m_a, 2=b_tilde+m_b
// ---------------------------------------------------------------------------
template <int MODE>
__device__ __forceinline__ void gemm_tile(const float* __restrict__ a,
                                          const float* __restrict__ bm,
                                          float* __restrict__ out,
                                          int bb, int m0, int n0) {
    constexpr int STG = (MODE == 0) ? STAGE0 : STAGE12;
    extern __shared__ char sm[];
    uint32_t su = (uint32_t)__cvta_generic_to_shared(sm);
    int t = threadIdx.x, wid = t >> 5, lane = t & 31;
    int wm = wid & 3, wn = wid >> 2;
    const size_t bo = (size_t)bb * S * S;

    const __half *Ah, *Al, *Bh, *Bl;
    if (MODE == 0) { Ah = g_a_hi + bo + (size_t)m0 * S; Al = g_a_lo + bo + (size_t)m0 * S;
                     Bh = g_b_hi + bo + (size_t)n0 * S; Bl = g_b_lo + bo + (size_t)n0 * S; }
    if (MODE == 1) { Ah = g_pa + bo + (size_t)m0 * S; Al = nullptr;
                     Bh = g_b_hi + bo + n0;           Bl = nullptr; }
    if (MODE == 2) { Ah = g_pb + bo + m0;             Al = nullptr;
                     Bh = g_a_hi + bo + n0;           Bl = nullptr; }

#define CPSTAGE(c) do {                                                          \
        uint32_t stu_ = su + ((c) & 3) * STG;                                    \
        if (MODE == 0) { cp_mk(Ah + (c) * 32, stu_, t);                          \
                         cp_mk(Al + (c) * 32, stu_ + 10240, t);                  \
                         cp_mk(Bh + (c) * 32, stu_ + 20480, t);                  \
                         cp_mk(Bl + (c) * 32, stu_ + 30720, t); }                \
        else if (MODE == 1) { cp_mk(Ah + (c) * 32, stu_, t);                     \
                              cp_kn(Bh + (size_t)(c) * 32 * S, stu_ + 10240, t);}\
        else           { cp_kn(Ah + (size_t)(c) * 32 * S, stu_, t);              \
                         cp_kn(Bh + (size_t)(c) * 32 * S, stu_ + 10240, t); }    \
        CP_COMMIT(); } while (0)

    float acc[2][4][4] = {};

    CPSTAGE(0); CPSTAGE(1); CPSTAGE(2);

#pragma unroll 1
    for (int c = 0; c < NC; ++c) {
        CP_WAIT(2);
        __syncthreads();
        if (c + 3 < NC) CPSTAGE(c + 3); else CP_COMMIT();
        compute_chunk<MODE>(su + (c & 3) * STG, acc, wm, wn, lane);
    }
    __syncthreads();

    int r  = lane >> 2;
    int cg = (lane & 3) * 2;

    if (MODE == 0) {
        float* Eb = g_E + bo;
#pragma unroll
        for (int mi = 0; mi < 2; ++mi)
#pragma unroll
            for (int nf = 0; nf < 4; ++nf) {
                int m = m0 + wm * 32 + mi * 16 + r;
                int n = n0 + wn * 32 + nf * 8 + cg;
                *(float2*)(Eb + (size_t)m * S + n)       = make_float2(acc[mi][nf][0], acc[mi][nf][1]);
                *(float2*)(Eb + (size_t)(m + 8) * S + n) = make_float2(acc[mi][nf][2], acc[mi][nf][3]);
            }
        return;
    }

    float* fs = (float*)sm;
#pragma unroll
    for (int mi = 0; mi < 2; ++mi)
#pragma unroll
        for (int nf = 0; nf < 4; ++nf) {
            int m = wm * 32 + mi * 16 + r;
            int n = wn * 32 + nf * 8 + cg;
            *(float2*)(fs + (size_t)m * PFS + n)       = make_float2(acc[mi][nf][0], acc[mi][nf][1]);
            *(float2*)(fs + (size_t)(m + 8) * PFS + n) = make_float2(acc[mi][nf][2], acc[mi][nf][3]);
        }
    __syncthreads();

    const float* base = (MODE == 1) ? (a + ((size_t)bb * S + m0) * S + n0)
                                    : (bm + ((size_t)bb * S + m0) * S + n0);
    size_t obase = ((size_t)bb * S + m0) * 2048 + n0;
    if (MODE == 2) obase += (size_t)NB * S * 2048;
    float* ob = out + obase;
#pragma unroll
    for (int p = 0; p < 8; ++p) {
        int idx = t + p * NT;
        int rr = idx >> 5, d4 = idx & 31;
        float4 xv = *(const float4*)(base + (size_t)rr * S + 4 * d4);
        float4 tv = *(const float4*)(fs + (size_t)rr * PFS + 4 * d4);
        float* o = ob + (size_t)rr * 2048 + 4 * d4;
        *(float4*)(o)        = xv;
        *(float4*)(o + 512)  = tv;
        *(float4*)(o + 1024) = make_float4(xv.x - tv.x, xv.y - tv.y, xv.z - tv.z, xv.w - tv.w);
        *(float4*)(o + 1536) = make_float4(xv.x * tv.x, xv.y * tv.y, xv.z * tv.z, xv.w * tv.w);
    }
#undef CPSTAGE
}

// ---------------------------------------------------------------------------
// Persistent GEMM kernels with dynamic tile scheduling
// ---------------------------------------------------------------------------
__global__ __launch_bounds__(NT)
void k_gemm0p(const float* __restrict__ a, const float* __restrict__ bm,
              float* __restrict__ out) {
    __shared__ unsigned task_s;
    for (;;) {
        if (threadIdx.x == 0) task_s = atomicAdd(&g_ctr0, 1u);
        __syncthreads();
        unsigned task = task_s;
        if (task >= 512u) break;
        int bb = task >> 4, m0 = ((task >> 2) & 3) * 128, n0 = (task & 3) * 128;
        gemm_tile<0>(a, bm, out, bb, m0, n0);
        __syncthreads();
    }
}

__global__ __launch_bounds__(NT)
void k_gemm12p(const float* __restrict__ a, const float* __restrict__ bm,
               float* __restrict__ out) {
    __shared__ unsigned task_s;
    for (;;) {
        if (threadIdx.x == 0) task_s = atomicAdd(&g_ctr12, 1u);
        __syncthreads();
        unsigned task = task_s;
        if (task >= 1024u) break;
        unsigned sub = task & 511u;
        int bb = sub >> 4, m0 = ((sub >> 2) & 3) * 128, n0 = (sub & 3) * 128;
        if (task < 512u) gemm_tile<1>(a, bm, out, bb, m0, n0);
        else             gemm_tile<2>(a, bm, out, bb, m0, n0);
        __syncthreads();
    }
}

// ---------------------------------------------------------------------------

extern "C" void kernel_launch(void* const* d_in, const int* in_sizes, int n_in,
                              void* d_out, int out_size) {
    const float* a  = (const float*)d_in[0];
    const float* bm = (const float*)d_in[1];
    float* out = (float*)d_out;
    (void)in_sizes; (void)n_in; (void)out_size;

    const int SMEM0  = NSTG * STAGE0;                 // 163840
    int smem12 = NSTG * STAGE12;                      // 75776
    if (smem12 < 128 * PFS * 4) smem12 = 128 * PFS * 4;

    static int configured = 0;
    if (!configured) {
        cudaFuncSetAttribute(k_gemm0p,  cudaFuncAttributeMaxDynamicSharedMemorySize, SMEM0);
        cudaFuncSetAttribute(k_gemm12p, cudaFuncAttributeMaxDynamicSharedMemorySize, smem12);
        configured = 1;
    }

    k_split<<<dim3(8192, 2), 256>>>(a, bm);
    k_gemm0p<<<PGRID, NT, SMEM0>>>(a, bm, out);
    k_row_stats<<<NB * S / 8, 256>>>();
    k_col_stats<<<dim3(S / 64, NB), 512>>>();
    k_pmat<<<dim3(S / 8, NB), 256>>>();
    k_gemm12p<<<PGRID, NT, smem12>>>(a, bm, out);
}